// round 2
// baseline (speedup 1.0000x reference)
#include <cuda_runtime.h>
#include <math.h>
#include <stdint.h>

#define NNODES 200000
#define NEDGES 440000
#define NGRAPHS 4096
#define EMBD 300
#define HID 600
#define C4 75            // EMBD/4
#define NLAYERS 5
#define TEMP_INV 25.0f
#define NBSCAN ((NNODES + 1 + 1023) / 1024)

// ---------------- scratch (device globals: no runtime allocation allowed) ----
__device__ float g_h[NNODES * EMBD];
__device__ float g_agg[NNODES * EMBD];
__device__ float g_t[NNODES * HID];
__device__ int   g_cnt[NNODES * 8];
__device__ int   g_rowptr[NNODES + 1];
__device__ int   g_cursor[NNODES + 2];
__device__ int   g_colidx[NEDGES];
__device__ int   g_bsums[256];
__device__ float g_bnsum[EMBD];
__device__ float g_bnss[EMBD];
__device__ float g_bnscale[EMBD];
__device__ float g_bnshift[EMBD];
__device__ float g_pool[NGRAPHS * EMBD];
__device__ int   g_gcnt[NGRAPHS];
__device__ float g_feat[2 * NGRAPHS * EMBD];

// ---------------- helpers ----------------
__device__ __forceinline__ float4 ld4(const float* p) {
    return *reinterpret_cast<const float4*>(p);
}
__device__ __forceinline__ void st4(float* p, float4 v) {
    *reinterpret_cast<float4*>(p) = v;
}
__device__ __forceinline__ float4 f4add(float4 a, float4 b) {
    return make_float4(a.x + b.x, a.y + b.y, a.z + b.z, a.w + b.w);
}
__device__ __forceinline__ float4 f4fma(float4 a, float s, float4 c) {
    return make_float4(fmaf(a.x, s, c.x), fmaf(a.y, s, c.y),
                       fmaf(a.z, s, c.z), fmaf(a.w, s, c.w));
}
__device__ __forceinline__ unsigned long long dup2(float a) {
    unsigned long long d;
    asm("mov.b64 %0, {%1, %1};" : "=l"(d) : "f"(a));
    return d;
}
__device__ __forceinline__ void fma2(unsigned long long& c,
                                     unsigned long long a,
                                     unsigned long long b) {
    asm("fma.rn.f32x2 %0, %1, %2, %0;" : "+l"(c) : "l"(a), "l"(b));
}
__device__ __forceinline__ float lo32(unsigned long long v) {
    return __uint_as_float((unsigned)(v & 0xffffffffull));
}
__device__ __forceinline__ float hi32(unsigned long long v) {
    return __uint_as_float((unsigned)(v >> 32));
}

// ---------------- graph structure ----------------
__global__ void zero_graphbufs_kernel() {
    int i = blockIdx.x * blockDim.x + threadIdx.x;
    int stride = gridDim.x * blockDim.x;
    for (int j = i; j < NNODES * 8; j += stride) g_cnt[j] = 0;
    for (int j = i; j <= NNODES; j += stride) g_cursor[j] = 0;
}

__global__ void edge_count_kernel(const int* __restrict__ ei,
                                  const int* __restrict__ ea) {
    int e = blockIdx.x * blockDim.x + threadIdx.x;
    if (e >= NEDGES) return;
    int dst = ei[NEDGES + e];
    atomicAdd(&g_cursor[dst], 1);
    atomicAdd(&g_cnt[dst * 8 + (ea[2 * e] & 3)], 1);
    atomicAdd(&g_cnt[dst * 8 + 4 + (ea[2 * e + 1] & 3)], 1);
}

__global__ void scan_blocks_kernel() {
    __shared__ int s[1024];
    int tid = threadIdx.x;
    int gid = blockIdx.x * 1024 + tid;
    int v = (gid <= NNODES) ? g_cursor[gid] : 0;
    s[tid] = v;
    __syncthreads();
    for (int off = 1; off < 1024; off <<= 1) {
        int t = (tid >= off) ? s[tid - off] : 0;
        __syncthreads();
        s[tid] += t;
        __syncthreads();
    }
    if (gid <= NNODES) g_rowptr[gid] = s[tid] - v;  // exclusive within block
    if (tid == 1023) g_bsums[blockIdx.x] = s[1023];
}

__global__ void scan_sums_kernel() {
    if (threadIdx.x == 0) {
        int acc = 0;
        for (int i = 0; i < NBSCAN; i++) {
            int t = g_bsums[i];
            g_bsums[i] = acc;
            acc += t;
        }
    }
}

__global__ void scan_add_kernel() {
    int gid = blockIdx.x * 1024 + threadIdx.x;
    if (gid <= NNODES) {
        int v = g_rowptr[gid] + g_bsums[blockIdx.x];
        g_rowptr[gid] = v;
        g_cursor[gid] = v;  // becomes fill cursor
    }
}

__global__ void fill_csr_kernel(const int* __restrict__ ei) {
    int e = blockIdx.x * blockDim.x + threadIdx.x;
    if (e >= NEDGES) return;
    int dst = ei[NEDGES + e];
    int pos = atomicAdd(&g_cursor[dst], 1);
    g_colidx[pos] = ei[e];  // src
}

// ---------------- features ----------------
__global__ void init_h_kernel(const int* __restrict__ x,
                              const float* __restrict__ ae1,
                              const float* __restrict__ ae2) {
    int idx = blockIdx.x * blockDim.x + threadIdx.x;
    if (idx >= NNODES * C4) return;
    int n = idx / C4, c = (idx % C4) * 4;
    float4 v = f4add(ld4(ae1 + x[2 * n] * EMBD + c),
                     ld4(ae2 + x[2 * n + 1] * EMBD + c));
    st4(g_h + n * EMBD + c, v);
}

// agg = sum_{edges->n} h[src]  +  count-weighted edge embeddings  +  h[n] + self_e
__global__ void agg_kernel(const float* __restrict__ ee1,
                           const float* __restrict__ ee2) {
    int idx = blockIdx.x * blockDim.x + threadIdx.x;
    if (idx >= NNODES * C4) return;
    int n = idx / C4, c = (idx % C4) * 4;
    float4 acc = ld4(g_h + n * EMBD + c);  // + h term (self message)
    int base = n * 8;
    float c00 = (float)g_cnt[base + 0];
    float c01 = (float)g_cnt[base + 1];
    float c02 = (float)g_cnt[base + 2];
    float c10 = (float)g_cnt[base + 4] + 1.0f;  // + self-loop dir 0
    float c11 = (float)g_cnt[base + 5];
    float c12 = (float)g_cnt[base + 6];
    acc = f4fma(ld4(ee1 + 0 * EMBD + c), c00, acc);
    acc = f4fma(ld4(ee1 + 1 * EMBD + c), c01, acc);
    acc = f4fma(ld4(ee1 + 2 * EMBD + c), c02, acc);
    acc = f4add(acc, ld4(ee1 + 4 * EMBD + c));  // self-loop bond type 4
    acc = f4fma(ld4(ee2 + 0 * EMBD + c), c10, acc);
    acc = f4fma(ld4(ee2 + 1 * EMBD + c), c11, acc);
    acc = f4fma(ld4(ee2 + 2 * EMBD + c), c12, acc);
    int rs = g_rowptr[n], re = g_rowptr[n + 1];
    for (int i = rs; i < re; i++) {
        int s = g_colidx[i];
        acc = f4add(acc, ld4(g_h + s * EMBD + c));
    }
    st4(g_agg + n * EMBD + c, acc);
}

// ---------------- GEMM (NN, row-major, f32x2 micro-kernel) ----------------
// C[M x N] = op(A[M x K] @ B[K x N] + bias), tile 64(M) x 128(N), 256 threads,
// thread tile 4m x 8n. Requires M % 64 == 0, K % 4 == 0. N guarded.
template <int RELU>
__global__ void gemm_nn(const float* __restrict__ A, const float* __restrict__ B,
                        const float* __restrict__ bias, float* __restrict__ C,
                        int M, int N, int K) {
    __shared__ float As[64][4];
    __shared__ float Bs[4][128];
    int tid = threadIdx.x;
    int tx = tid & 15, ty = tid >> 4;
    int m0 = blockIdx.y * 64;
    int n0 = blockIdx.x * 128;
    int la_m = tid >> 2, la_k = tid & 3;
    int lb_k = tid >> 6, lb_n = (tid & 63) * 2;

    unsigned long long acc[4][4];
#pragma unroll
    for (int i = 0; i < 4; i++)
#pragma unroll
        for (int j = 0; j < 4; j++) acc[i][j] = 0ull;

    const float* Aptr = A + (long long)(m0 + la_m) * K + la_k;
    int bn = n0 + lb_n;

    for (int k0 = 0; k0 < K; k0 += 4) {
        As[la_m][la_k] = Aptr[k0];
        float b0 = (bn < N) ? B[(long long)(k0 + lb_k) * N + bn] : 0.f;
        float b1 = (bn + 1 < N) ? B[(long long)(k0 + lb_k) * N + bn + 1] : 0.f;
        *reinterpret_cast<float2*>(&Bs[lb_k][lb_n]) = make_float2(b0, b1);
        __syncthreads();
#pragma unroll
        for (int kk = 0; kk < 4; kk++) {
            ulonglong2 q0 = *reinterpret_cast<const ulonglong2*>(&Bs[kk][tx * 8]);
            ulonglong2 q1 = *reinterpret_cast<const ulonglong2*>(&Bs[kk][tx * 8 + 4]);
#pragma unroll
            for (int i = 0; i < 4; i++) {
                unsigned long long ad = dup2(As[ty * 4 + i][kk]);
                fma2(acc[i][0], ad, q0.x);
                fma2(acc[i][1], ad, q0.y);
                fma2(acc[i][2], ad, q1.x);
                fma2(acc[i][3], ad, q1.y);
            }
        }
        __syncthreads();
    }

    int nb = n0 + tx * 8;
#pragma unroll
    for (int i = 0; i < 4; i++) {
        float* crow = C + (long long)(m0 + ty * 4 + i) * N + nb;
#pragma unroll
        for (int j = 0; j < 4; j++) {
            int n = nb + j * 2;
            if (n < N) {
                float v = lo32(acc[i][j]) + bias[n];
                if (RELU) v = fmaxf(v, 0.f);
                crow[j * 2] = v;
            }
            if (n + 1 < N) {
                float v = hi32(acc[i][j]) + bias[n + 1];
                if (RELU) v = fmaxf(v, 0.f);
                crow[j * 2 + 1] = v;
            }
        }
    }
}

// ---------------- GEMM (NT, for logits): C = scale * A @ B^T ----------------
// A[M x K], B[N x K] row-major. Requires M%64==0, N%128==0, K%4==0.
__global__ void gemm_nt_scale(const float* __restrict__ A, const float* __restrict__ B,
                              float* __restrict__ C, int M, int N, int K, float scale) {
    __shared__ float As[64][4];
    __shared__ float Bs[4][132];
    int tid = threadIdx.x;
    int tx = tid & 15, ty = tid >> 4;
    int m0 = blockIdx.y * 64;
    int n0 = blockIdx.x * 128;
    int la_m = tid >> 2, la_k = tid & 3;
    int lb_n = tid >> 1, lb_k0 = (tid & 1) * 2;

    unsigned long long acc[4][4];
#pragma unroll
    for (int i = 0; i < 4; i++)
#pragma unroll
        for (int j = 0; j < 4; j++) acc[i][j] = 0ull;

    const float* Aptr = A + (long long)(m0 + la_m) * K + la_k;
    const float* Bptr = B + (long long)(n0 + lb_n) * K + lb_k0;

    for (int k0 = 0; k0 < K; k0 += 4) {
        As[la_m][la_k] = Aptr[k0];
        float2 bv = *reinterpret_cast<const float2*>(Bptr + k0);
        Bs[lb_k0][lb_n] = bv.x;
        Bs[lb_k0 + 1][lb_n] = bv.y;
        __syncthreads();
#pragma unroll
        for (int kk = 0; kk < 4; kk++) {
            ulonglong2 q0 = *reinterpret_cast<const ulonglong2*>(&Bs[kk][tx * 8]);
            ulonglong2 q1 = *reinterpret_cast<const ulonglong2*>(&Bs[kk][tx * 8 + 4]);
#pragma unroll
            for (int i = 0; i < 4; i++) {
                unsigned long long ad = dup2(As[ty * 4 + i][kk]);
                fma2(acc[i][0], ad, q0.x);
                fma2(acc[i][1], ad, q0.y);
                fma2(acc[i][2], ad, q1.x);
                fma2(acc[i][3], ad, q1.y);
            }
        }
        __syncthreads();
    }

    int nb = n0 + tx * 8;
#pragma unroll
    for (int i = 0; i < 4; i++) {
        float* crow = C + (long long)(m0 + ty * 4 + i) * N + nb;
#pragma unroll
        for (int j = 0; j < 4; j++) {
            crow[j * 2] = lo32(acc[i][j]) * scale;
            crow[j * 2 + 1] = hi32(acc[i][j]) * scale;
        }
    }
}

// ---------------- BatchNorm ----------------
__global__ void zero_bn_kernel() {
    int c = threadIdx.x;
    if (c < EMBD) { g_bnsum[c] = 0.f; g_bnss[c] = 0.f; }
}

__global__ void bn_stats_kernel() {
    int c = threadIdx.x;  // blockDim.x == EMBD
    int r0 = blockIdx.x * 512;
    int r1 = min(r0 + 512, NNODES);
    float s = 0.f, ss = 0.f;
    for (int r = r0; r < r1; r++) {
        float v = g_h[(long long)r * EMBD + c];
        s += v;
        ss += v * v;
    }
    atomicAdd(&g_bnsum[c], s);
    atomicAdd(&g_bnss[c], ss);
}

__global__ void bn_finalize_kernel(const float* __restrict__ gamma,
                                   const float* __restrict__ beta) {
    int c = threadIdx.x;
    if (c >= EMBD) return;
    float mean = g_bnsum[c] * (1.0f / NNODES);
    float var = g_bnss[c] * (1.0f / NNODES) - mean * mean;
    float rs = rsqrtf(var + 1e-5f);
    float sc = rs * gamma[c];
    g_bnscale[c] = sc;
    g_bnshift[c] = beta[c] - mean * sc;
}

__global__ void bn_apply_kernel(int doRelu) {
    int idx = blockIdx.x * blockDim.x + threadIdx.x;
    if (idx >= NNODES * C4) return;
    int n = idx / C4, c = (idx % C4) * 4;
    float4 v = ld4(g_h + n * EMBD + c);
    float4 sc = ld4(g_bnscale + c);
    float4 sh = ld4(g_bnshift + c);
    v.x = fmaf(v.x, sc.x, sh.x);
    v.y = fmaf(v.y, sc.y, sh.y);
    v.z = fmaf(v.z, sc.z, sh.z);
    v.w = fmaf(v.w, sc.w, sh.w);
    if (doRelu) {
        v.x = fmaxf(v.x, 0.f); v.y = fmaxf(v.y, 0.f);
        v.z = fmaxf(v.z, 0.f); v.w = fmaxf(v.w, 0.f);
    }
    st4(g_h + n * EMBD + c, v);
}

// ---------------- pooling ----------------
__global__ void zero_pool_kernel() {
    int i = blockIdx.x * blockDim.x + threadIdx.x;
    if (i < NGRAPHS * EMBD) g_pool[i] = 0.f;
    if (i < NGRAPHS) g_gcnt[i] = 0;
}

__global__ void gcount_kernel(const int* __restrict__ bi) {
    int n = blockIdx.x * blockDim.x + threadIdx.x;
    if (n < NNODES) atomicAdd(&g_gcnt[bi[n]], 1);
}

__global__ void pool_kernel(const int* __restrict__ bi) {
    int idx = blockIdx.x * blockDim.x + threadIdx.x;
    if (idx >= NNODES * C4) return;
    int n = idx / C4, c = (idx % C4) * 4;
    int g = bi[n];
    float4 v = ld4(g_h + n * EMBD + c);
    float* d = g_pool + g * EMBD + c;
    atomicAdd(d + 0, v.x);
    atomicAdd(d + 1, v.y);
    atomicAdd(d + 2, v.z);
    atomicAdd(d + 3, v.w);
}

__global__ void pool_div_kernel() {
    int i = blockIdx.x * blockDim.x + threadIdx.x;
    if (i >= NGRAPHS * EMBD) return;
    int g = i / EMBD;
    float cnt = fmaxf((float)g_gcnt[g], 1.0f);
    g_pool[i] /= cnt;
}

// ---------------- L2 row normalize ----------------
__global__ void normalize_kernel(float* __restrict__ f) {
    __shared__ float red[4];
    long long r = blockIdx.x;
    float* row = f + r * EMBD;
    float ss = 0.f;
    for (int c = threadIdx.x; c < EMBD; c += 128) {
        float v = row[c];
        ss += v * v;
    }
    for (int o = 16; o; o >>= 1) ss += __shfl_down_sync(0xffffffffu, ss, o);
    if ((threadIdx.x & 31) == 0) red[threadIdx.x >> 5] = ss;
    __syncthreads();
    if (threadIdx.x == 0) red[0] = rsqrtf(red[0] + red[1] + red[2] + red[3]);
    __syncthreads();
    float s = red[0];
    for (int c = threadIdx.x; c < EMBD; c += 128) row[c] *= s;
}

__global__ void labels_kernel(float* __restrict__ out, int extra) {
    int i = blockIdx.x * blockDim.x + threadIdx.x;
    if (i < extra) out[i] = (float)i;
}

// ---------------- host orchestration ----------------
extern "C" void kernel_launch(void* const* d_in, const int* in_sizes, int n_in,
                              void* d_out, int out_size) {
    const float* ae1 = (const float*)d_in[8];
    const float* ae2 = (const float*)d_in[9];
    const float* ee1 = (const float*)d_in[10];  // [5,6,300]
    const float* ee2 = (const float*)d_in[11];  // [5,3,300]
    const float* W1 = (const float*)d_in[12];   // [5,300,600]
    const float* bm1 = (const float*)d_in[13];  // [5,600]
    const float* W2 = (const float*)d_in[14];   // [5,600,300]
    const float* bm2 = (const float*)d_in[15];  // [5,300]
    const float* gamma = (const float*)d_in[16];
    const float* beta = (const float*)d_in[17];
    const float* Wp1 = (const float*)d_in[18];
    const float* bp1 = (const float*)d_in[19];
    const float* Wp2 = (const float*)d_in[20];
    const float* bp2 = (const float*)d_in[21];

    float *h, *agg, *t, *pool, *feat;
    cudaGetSymbolAddress((void**)&h, g_h);
    cudaGetSymbolAddress((void**)&agg, g_agg);
    cudaGetSymbolAddress((void**)&t, g_t);
    cudaGetSymbolAddress((void**)&pool, g_pool);
    cudaGetSymbolAddress((void**)&feat, g_feat);

    const int GN = (NNODES * C4 + 255) / 256;
    const int GE = (NEDGES + 255) / 256;
    const int GP = (NGRAPHS * EMBD + 255) / 256;

    for (int enc = 0; enc < 2; enc++) {
        const int* x = (const int*)d_in[enc * 4 + 0];
        const int* ei = (const int*)d_in[enc * 4 + 1];
        const int* ea = (const int*)d_in[enc * 4 + 2];
        const int* bi = (const int*)d_in[enc * 4 + 3];

        // CSR + attr counts
        zero_graphbufs_kernel<<<2048, 256>>>();
        edge_count_kernel<<<GE, 256>>>(ei, ea);
        scan_blocks_kernel<<<NBSCAN, 1024>>>();
        scan_sums_kernel<<<1, 32>>>();
        scan_add_kernel<<<NBSCAN, 1024>>>();
        fill_csr_kernel<<<GE, 256>>>(ei);

        init_h_kernel<<<GN, 256>>>(x, ae1, ae2);

        for (int l = 0; l < NLAYERS; l++) {
            agg_kernel<<<GN, 256>>>(ee1 + l * 6 * EMBD, ee2 + l * 3 * EMBD);
            gemm_nn<1><<<dim3(5, NNODES / 64), 256>>>(
                agg, W1 + (long long)l * EMBD * HID, bm1 + l * HID, t,
                NNODES, HID, EMBD);
            gemm_nn<0><<<dim3(3, NNODES / 64), 256>>>(
                t, W2 + (long long)l * HID * EMBD, bm2 + l * EMBD, h,
                NNODES, EMBD, HID);
            zero_bn_kernel<<<1, 512>>>();
            bn_stats_kernel<<<(NNODES + 511) / 512, EMBD>>>();
            bn_finalize_kernel<<<1, 512>>>(gamma + l * EMBD, beta + l * EMBD);
            bn_apply_kernel<<<GN, 256>>>(l < NLAYERS - 1 ? 1 : 0);
        }

        // mean pool
        zero_pool_kernel<<<GP, 256>>>();
        gcount_kernel<<<(NNODES + 255) / 256, 256>>>(bi);
        pool_kernel<<<GN, 256>>>(bi);
        pool_div_kernel<<<GP, 256>>>();

        // projection head
        gemm_nn<1><<<dim3(3, NGRAPHS / 64), 256>>>(pool, Wp1, bp1, t,
                                                   NGRAPHS, EMBD, EMBD);
        gemm_nn<0><<<dim3(3, NGRAPHS / 64), 256>>>(
            t, Wp2, bp2, feat + (long long)enc * NGRAPHS * EMBD,
            NGRAPHS, EMBD, EMBD);
    }

    normalize_kernel<<<2 * NGRAPHS, 128>>>(feat);

    gemm_nt_scale<<<dim3(NGRAPHS / 128, NGRAPHS / 64), 256>>>(
        feat, feat + (long long)NGRAPHS * EMBD, (float*)d_out,
        NGRAPHS, NGRAPHS, EMBD, TEMP_INV);

    long long logits_elems = (long long)NGRAPHS * NGRAPHS;
    int extra = (int)((long long)out_size - logits_elems);
    if (extra > 0)
        labels_kernel<<<(extra + 255) / 256, 256>>>(
            (float*)d_out + logits_elems, extra);
}

// round 4
// speedup vs baseline: 3.4939x; 3.4939x over previous
#include <cuda_runtime.h>
#include <cuda_bf16.h>
#include <math.h>
#include <stdint.h>

#define NNODES 200000
#define NEDGES 440000
#define NGRAPHS 4096
#define EMBD 300
#define HID 600
#define C4 75
#define NLAYERS 5
#define TEMP_INV 25.0f
#define NBSCAN ((NNODES + 1 + 1023) / 1024)

#define LDH 320
#define LDT 640
#define MPAD 200064             // 1563 * 128

// ---------------- scratch ----------------
__device__ float g_h[MPAD * LDH];
__device__ __align__(16) __nv_bfloat16 g_ahi[(size_t)MPAD * LDH];
__device__ __align__(16) __nv_bfloat16 g_alo[(size_t)MPAD * LDH];
__device__ __align__(16) __nv_bfloat16 g_thi[(size_t)MPAD * LDT];
__device__ __align__(16) __nv_bfloat16 g_tlo[(size_t)MPAD * LDT];
__device__ __align__(16) __nv_bfloat16 g_whi[640 * 320];
__device__ __align__(16) __nv_bfloat16 g_wlo[640 * 320];
__device__ int   g_cnt[NNODES * 8];
__device__ int   g_rowptr[NNODES + 1];
__device__ int   g_cursor[NNODES + 2];
__device__ int   g_colidx[NEDGES];
__device__ int   g_bsums[256];
__device__ float g_bnsum[EMBD];
__device__ float g_bnss[EMBD];
__device__ float g_bnscale[EMBD];
__device__ float g_bnshift[EMBD];
__device__ float g_pool[NGRAPHS * LDH];
__device__ int   g_gcnt[NGRAPHS];
__device__ float g_feat[2 * NGRAPHS * LDH];

// ---------------- helpers ----------------
__device__ __forceinline__ float4 ld4(const float* p) {
    return *reinterpret_cast<const float4*>(p);
}
__device__ __forceinline__ void st4(float* p, float4 v) {
    *reinterpret_cast<float4*>(p) = v;
}
__device__ __forceinline__ float4 f4add(float4 a, float4 b) {
    return make_float4(a.x + b.x, a.y + b.y, a.z + b.z, a.w + b.w);
}
__device__ __forceinline__ float4 f4fma(float4 a, float s, float4 c) {
    return make_float4(fmaf(a.x, s, c.x), fmaf(a.y, s, c.y),
                       fmaf(a.z, s, c.z), fmaf(a.w, s, c.w));
}
__device__ __forceinline__ unsigned long long dup2(float a) {
    unsigned long long d;
    asm("mov.b64 %0, {%1, %1};" : "=l"(d) : "f"(a));
    return d;
}
__device__ __forceinline__ void fma2(unsigned long long& c,
                                     unsigned long long a,
                                     unsigned long long b) {
    asm("fma.rn.f32x2 %0, %1, %2, %0;" : "+l"(c) : "l"(a), "l"(b));
}
__device__ __forceinline__ float lo32(unsigned long long v) {
    return __uint_as_float((unsigned)(v & 0xffffffffull));
}
__device__ __forceinline__ float hi32(unsigned long long v) {
    return __uint_as_float((unsigned)(v >> 32));
}
__device__ __forceinline__ uint32_t smem_u32(const void* p) {
    uint32_t a;
    asm("{ .reg .u64 t; cvta.to.shared.u64 t, %1; cvt.u32.u64 %0, t; }"
        : "=r"(a) : "l"(p));
    return a;
}
__device__ __forceinline__ void cpasync16(uint32_t dst, const void* src) {
    asm volatile("cp.async.cg.shared.global [%0], [%1], 16;"
                 :: "r"(dst), "l"(src));
}

#define LDSM_X4(r0, r1, r2, r3, addr) \
    asm volatile("ldmatrix.sync.aligned.m8n8.x4.shared.b16 {%0,%1,%2,%3}, [%4];" \
                 : "=r"(r0), "=r"(r1), "=r"(r2), "=r"(r3) : "r"(addr))

#define MMA16816(c, a, b0, b1) \
    asm volatile("mma.sync.aligned.m16n8k16.row.col.f32.bf16.bf16.f32 " \
                 "{%0,%1,%2,%3}, {%4,%5,%6,%7}, {%8,%9}, {%0,%1,%2,%3};" \
                 : "+f"((c)[0]), "+f"((c)[1]), "+f"((c)[2]), "+f"((c)[3]) \
                 : "r"((a)[0]), "r"((a)[1]), "r"((a)[2]), "r"((a)[3]), \
                   "r"(b0), "r"(b1))

// smem stage layout: AH 16K | AL 16K | BH 16K | BL 16K = 64K per stage, 2 stages
#define SM_AH 0
#define SM_AL 16384
#define SM_BH 32768
#define SM_BL 49152
#define STAGE 65536
#define GEMM_SMEM (2 * STAGE)

// ---------------- weight convert: W[K,N] fp32 -> Bt[Npad,Kpad] bf16 hi/lo ----
__global__ void convert_w_kernel(const float* __restrict__ W, int Kreal, int Nreal,
                                 int Kpad, int Npad,
                                 __nv_bfloat16* __restrict__ hi,
                                 __nv_bfloat16* __restrict__ lo) {
    int idx = blockIdx.x * blockDim.x + threadIdx.x;
    if (idx >= Kpad * Npad) return;
    int n = idx / Kpad, k = idx % Kpad;
    float v = (k < Kreal && n < Nreal) ? W[k * Nreal + n] : 0.f;
    __nv_bfloat16 h = __float2bfloat16_rn(v);
    float r = v - __bfloat162float(h);
    hi[idx] = h;
    lo[idx] = __float2bfloat16_rn(r);
}

__global__ void convert_pool_kernel(const float* __restrict__ pool,
                                    __nv_bfloat16* __restrict__ hi,
                                    __nv_bfloat16* __restrict__ lo) {
    int idx = blockIdx.x * blockDim.x + threadIdx.x;
    if (idx >= NGRAPHS * LDH) return;
    float v = pool[idx];
    __nv_bfloat16 h = __float2bfloat16_rn(v);
    hi[idx] = h;
    lo[idx] = __float2bfloat16_rn(v - __bfloat162float(h));
}

// ---------------- stage loader (cp.async, SW128 swizzle) ----------------
__device__ __forceinline__ void gemm_load_stage(
    uint32_t sbase, int tid, int m0, int n0, int k0,
    const __nv_bfloat16* Ahi, const __nv_bfloat16* Alo, int lda,
    const __nv_bfloat16* Bhi, const __nv_bfloat16* Blo, int Kpad, int Npad) {
#pragma unroll
    for (int it = 0; it < 4; it++) {
        int L = it * 256 + tid;       // 0..1023
        int row = L >> 3, j = L & 7;
        uint32_t soff = (uint32_t)row * 128 +
                        (((uint32_t)j * 16) ^ (((uint32_t)(row & 7)) << 4));
        size_t aoff = (size_t)(m0 + row) * lda + k0 + j * 8;
        int brow = n0 + row;
        brow = brow < Npad ? brow : Npad - 1;
        size_t boff = (size_t)brow * Kpad + k0 + j * 8;
        cpasync16(sbase + SM_AH + soff, Ahi + aoff);
        cpasync16(sbase + SM_AL + soff, Alo + aoff);
        cpasync16(sbase + SM_BH + soff, Bhi + boff);
        cpasync16(sbase + SM_BL + soff, Blo + boff);
    }
    asm volatile("cp.async.commit_group;" ::: "memory");
}

// ---------------- split-bf16 mma.sync GEMM ----------------
// C[M x ldc] = op(A @ Bt^T + bias). A split bf16 [M x lda], Bt split [Npad x Kpad].
// Tiles: CTA 128x128xK, warp 64x32, mma m16n8k16. grid = (ceil(ldc/128), M/128).
template <int RELU, int SPLITOUT>
__global__ void __launch_bounds__(256, 1)
mma_gemm(const __nv_bfloat16* __restrict__ Ahi, const __nv_bfloat16* __restrict__ Alo,
         int lda, int Kpad,
         const __nv_bfloat16* __restrict__ Bhi, const __nv_bfloat16* __restrict__ Blo,
         int Npad, const float* __restrict__ bias,
         float* __restrict__ C, __nv_bfloat16* __restrict__ Chi,
         __nv_bfloat16* __restrict__ Clo, int ldc, int Nreal) {
    extern __shared__ char smem[];
    uint32_t sb = smem_u32(smem);
    int tid = threadIdx.x;
    int m0 = blockIdx.y * 128, n0 = blockIdx.x * 128;
    int nchunks = Kpad >> 6;

    gemm_load_stage(sb, tid, m0, n0, 0, Ahi, Alo, lda, Bhi, Blo, Kpad, Npad);
    gemm_load_stage(sb + STAGE, tid, m0, n0, 64, Ahi, Alo, lda, Bhi, Blo, Kpad, Npad);

    int lane = tid & 31, wid = tid >> 5;
    int wm = wid & 1, wn = wid >> 1;

    float acc[4][4][4];
#pragma unroll
    for (int i = 0; i < 4; i++)
#pragma unroll
        for (int j = 0; j < 4; j++)
#pragma unroll
            for (int r = 0; r < 4; r++) acc[i][j][r] = 0.f;

    uint32_t mask = ((uint32_t)(lane & 7)) << 4;
    uint32_t a_row_off[4];
#pragma unroll
    for (int i = 0; i < 4; i++)
        a_row_off[i] = (uint32_t)(wm * 64 + i * 16 + (lane & 15)) * 128;
    uint32_t a_kb_base = (uint32_t)((lane >> 4) * 16);
    int g = lane >> 3;
    uint32_t b_row_off[2];
#pragma unroll
    for (int q = 0; q < 2; q++)
        b_row_off[q] = (uint32_t)(wn * 32 + q * 16 + (g >> 1) * 8 + (lane & 7)) * 128;
    uint32_t b_kb_base = (uint32_t)((g & 1) * 16);

    for (int ch = 0; ch < nchunks; ch++) {
        asm volatile("cp.async.wait_group 1;" ::: "memory");
        __syncthreads();
        uint32_t st = sb + (uint32_t)(ch & 1) * STAGE;
#pragma unroll
        for (int s = 0; s < 4; s++) {
            uint32_t ah[4][4], alr[4][4], bh[2][4], bl[2][4];
            uint32_t akb = (a_kb_base + s * 32) ^ mask;
            uint32_t bkb = (b_kb_base + s * 32) ^ mask;
#pragma unroll
            for (int i = 0; i < 4; i++) {
                uint32_t ad = st + SM_AH + a_row_off[i] + akb;
                LDSM_X4(ah[i][0], ah[i][1], ah[i][2], ah[i][3], ad);
                uint32_t ad2 = st + SM_AL + a_row_off[i] + akb;
                LDSM_X4(alr[i][0], alr[i][1], alr[i][2], alr[i][3], ad2);
            }
#pragma unroll
            for (int q = 0; q < 2; q++) {
                uint32_t bd = st + SM_BH + b_row_off[q] + bkb;
                LDSM_X4(bh[q][0], bh[q][1], bh[q][2], bh[q][3], bd);
                uint32_t bd2 = st + SM_BL + b_row_off[q] + bkb;
                LDSM_X4(bl[q][0], bl[q][1], bl[q][2], bl[q][3], bd2);
            }
#pragma unroll
            for (int i = 0; i < 4; i++)
#pragma unroll
                for (int j = 0; j < 4; j++) {
                    int q = j >> 1, t = (j & 1) * 2;
                    MMA16816(acc[i][j], ah[i], bh[q][t], bh[q][t + 1]);
                    MMA16816(acc[i][j], ah[i], bl[q][t], bl[q][t + 1]);
                    MMA16816(acc[i][j], alr[i], bh[q][t], bh[q][t + 1]);
                }
        }
        __syncthreads();
        if (ch + 2 < nchunks)
            gemm_load_stage(st, tid, m0, n0, (ch + 2) * 64,
                            Ahi, Alo, lda, Bhi, Blo, Kpad, Npad);
        else
            asm volatile("cp.async.commit_group;" ::: "memory");
    }

    // ---- epilogue ----
#pragma unroll
    for (int i = 0; i < 4; i++) {
        int r0 = m0 + wm * 64 + i * 16 + (lane >> 2);
#pragma unroll
        for (int j = 0; j < 4; j++) {
            int col = n0 + wn * 32 + j * 8 + (lane & 3) * 2;
            if (col >= ldc) continue;
            float b0 = (col < Nreal) ? bias[col] : 0.f;
            float b1 = (col + 1 < Nreal) ? bias[col + 1] : 0.f;
            float v00 = (col < Nreal) ? acc[i][j][0] + b0 : 0.f;
            float v01 = (col + 1 < Nreal) ? acc[i][j][1] + b1 : 0.f;
            float v10 = (col < Nreal) ? acc[i][j][2] + b0 : 0.f;
            float v11 = (col + 1 < Nreal) ? acc[i][j][3] + b1 : 0.f;
            if (RELU) {
                v00 = fmaxf(v00, 0.f); v01 = fmaxf(v01, 0.f);
                v10 = fmaxf(v10, 0.f); v11 = fmaxf(v11, 0.f);
            }
            if (SPLITOUT) {
                __nv_bfloat16 h00 = __float2bfloat16_rn(v00);
                __nv_bfloat16 h01 = __float2bfloat16_rn(v01);
                __nv_bfloat16 h10 = __float2bfloat16_rn(v10);
                __nv_bfloat16 h11 = __float2bfloat16_rn(v11);
                __nv_bfloat162 hh0; hh0.x = h00; hh0.y = h01;
                __nv_bfloat162 hh1; hh1.x = h10; hh1.y = h11;
                __nv_bfloat162 ll0;
                ll0.x = __float2bfloat16_rn(v00 - __bfloat162float(h00));
                ll0.y = __float2bfloat16_rn(v01 - __bfloat162float(h01));
                __nv_bfloat162 ll1;
                ll1.x = __float2bfloat16_rn(v10 - __bfloat162float(h10));
                ll1.y = __float2bfloat16_rn(v11 - __bfloat162float(h11));
                *reinterpret_cast<__nv_bfloat162*>(Chi + (size_t)r0 * ldc + col) = hh0;
                *reinterpret_cast<__nv_bfloat162*>(Clo + (size_t)r0 * ldc + col) = ll0;
                *reinterpret_cast<__nv_bfloat162*>(Chi + (size_t)(r0 + 8) * ldc + col) = hh1;
                *reinterpret_cast<__nv_bfloat162*>(Clo + (size_t)(r0 + 8) * ldc + col) = ll1;
            } else {
                *reinterpret_cast<float2*>(C + (size_t)r0 * ldc + col) =
                    make_float2(v00, v01);
                *reinterpret_cast<float2*>(C + (size_t)(r0 + 8) * ldc + col) =
                    make_float2(v10, v11);
            }
        }
    }
}

// ---------------- graph structure ----------------
__global__ void zero_graphbufs_kernel() {
    int i = blockIdx.x * blockDim.x + threadIdx.x;
    int stride = gridDim.x * blockDim.x;
    for (int j = i; j < NNODES * 8; j += stride) g_cnt[j] = 0;
    for (int j = i; j <= NNODES; j += stride) g_cursor[j] = 0;
}

__global__ void edge_count_kernel(const int* __restrict__ ei,
                                  const int* __restrict__ ea) {
    int e = blockIdx.x * blockDim.x + threadIdx.x;
    if (e >= NEDGES) return;
    int dst = ei[NEDGES + e];
    atomicAdd(&g_cursor[dst], 1);
    atomicAdd(&g_cnt[dst * 8 + (ea[2 * e] & 3)], 1);
    atomicAdd(&g_cnt[dst * 8 + 4 + (ea[2 * e + 1] & 3)], 1);
}

__global__ void scan_blocks_kernel() {
    __shared__ int s[1024];
    int tid = threadIdx.x;
    int gid = blockIdx.x * 1024 + tid;
    int v = (gid <= NNODES) ? g_cursor[gid] : 0;
    s[tid] = v;
    __syncthreads();
    for (int off = 1; off < 1024; off <<= 1) {
        int t = (tid >= off) ? s[tid - off] : 0;
        __syncthreads();
        s[tid] += t;
        __syncthreads();
    }
    if (gid <= NNODES) g_rowptr[gid] = s[tid] - v;
    if (tid == 1023) g_bsums[blockIdx.x] = s[1023];
}

__global__ void scan_sums_kernel() {
    if (threadIdx.x == 0) {
        int acc = 0;
        for (int i = 0; i < NBSCAN; i++) {
            int t = g_bsums[i];
            g_bsums[i] = acc;
            acc += t;
        }
    }
}

__global__ void scan_add_kernel() {
    int gid = blockIdx.x * 1024 + threadIdx.x;
    if (gid <= NNODES) {
        int v = g_rowptr[gid] + g_bsums[blockIdx.x];
        g_rowptr[gid] = v;
        g_cursor[gid] = v;
    }
}

__global__ void fill_csr_kernel(const int* __restrict__ ei) {
    int e = blockIdx.x * blockDim.x + threadIdx.x;
    if (e >= NEDGES) return;
    int dst = ei[NEDGES + e];
    int pos = atomicAdd(&g_cursor[dst], 1);
    g_colidx[pos] = ei[e];
}

// ---------------- features ----------------
__global__ void init_h_kernel(const int* __restrict__ x,
                              const float* __restrict__ ae1,
                              const float* __restrict__ ae2) {
    int idx = blockIdx.x * blockDim.x + threadIdx.x;
    if (idx >= NNODES * C4) return;
    int n = idx / C4, c = (idx % C4) * 4;
    float4 v = f4add(ld4(ae1 + x[2 * n] * EMBD + c),
                     ld4(ae2 + x[2 * n + 1] * EMBD + c));
    st4(g_h + (size_t)n * LDH + c, v);
}

// agg -> split bf16 directly (GEMM1 input)
__global__ void agg_kernel(const float* __restrict__ ee1,
                           const float* __restrict__ ee2) {
    int idx = blockIdx.x * blockDim.x + threadIdx.x;
    if (idx >= NNODES * 80) return;
    int n = idx / 80, c4 = idx % 80;
    int c = c4 * 4;
    size_t o = (size_t)n * LDH + c;
    if (c4 >= C4) {
        *reinterpret_cast<uint2*>(&g_ahi[o]) = make_uint2(0u, 0u);
        *reinterpret_cast<uint2*>(&g_alo[o]) = make_uint2(0u, 0u);
        return;
    }
    float4 acc = ld4(g_h + o);
    int base = n * 8;
    float c00 = (float)g_cnt[base + 0];
    float c01 = (float)g_cnt[base + 1];
    float c02 = (float)g_cnt[base + 2];
    float c10 = (float)g_cnt[base + 4] + 1.0f;
    float c11 = (float)g_cnt[base + 5];
    float c12 = (float)g_cnt[base + 6];
    acc = f4fma(ld4(ee1 + 0 * EMBD + c), c00, acc);
    acc = f4fma(ld4(ee1 + 1 * EMBD + c), c01, acc);
    acc = f4fma(ld4(ee1 + 2 * EMBD + c), c02, acc);
    acc = f4add(acc, ld4(ee1 + 4 * EMBD + c));
    acc = f4fma(ld4(ee2 + 0 * EMBD + c), c10, acc);
    acc = f4fma(ld4(ee2 + 1 * EMBD + c), c11, acc);
    acc = f4fma(ld4(ee2 + 2 * EMBD + c), c12, acc);
    int rs = g_rowptr[n], re = g_rowptr[n + 1];
    for (int i = rs; i < re; i++) {
        int s = g_colidx[i];
        acc = f4add(acc, ld4(g_h + (size_t)s * LDH + c));
    }
    __nv_bfloat162 h01 = __floats2bfloat162_rn(acc.x, acc.y);
    __nv_bfloat162 h23 = __floats2bfloat162_rn(acc.z, acc.w);
    __nv_bfloat162 l01 = __floats2bfloat162_rn(acc.x - __bfloat162float(h01.x),
                                               acc.y - __bfloat162float(h01.y));
    __nv_bfloat162 l23 = __floats2bfloat162_rn(acc.z - __bfloat162float(h23.x),
                                               acc.w - __bfloat162float(h23.y));
    *reinterpret_cast<uint2*>(&g_ahi[o]) =
        make_uint2(*reinterpret_cast<uint32_t*>(&h01),
                   *reinterpret_cast<uint32_t*>(&h23));
    *reinterpret_cast<uint2*>(&g_alo[o]) =
        make_uint2(*reinterpret_cast<uint32_t*>(&l01),
                   *reinterpret_cast<uint32_t*>(&l23));
}

// ---------------- logits GEMM (f32x2, NT): C = scale * A @ B^T --------------
__global__ void gemm_nt_scale(const float* __restrict__ A, const float* __restrict__ B,
                              float* __restrict__ C, int M, int N, int K, int lda,
                              float scale) {
    __shared__ float As[64][4];
    __shared__ float Bs[4][132];
    int tid = threadIdx.x;
    int tx = tid & 15, ty = tid >> 4;
    int m0 = blockIdx.y * 64;
    int n0 = blockIdx.x * 128;
    int la_m = tid >> 2, la_k = tid & 3;
    int lb_n = tid >> 1, lb_k0 = (tid & 1) * 2;

    unsigned long long acc[4][4];
#pragma unroll
    for (int i = 0; i < 4; i++)
#pragma unroll
        for (int j = 0; j < 4; j++) acc[i][j] = 0ull;

    const float* Aptr = A + (size_t)(m0 + la_m) * lda + la_k;
    const float* Bptr = B + (size_t)(n0 + lb_n) * lda + lb_k0;

    for (int k0 = 0; k0 < K; k0 += 4) {
        As[la_m][la_k] = Aptr[k0];
        float2 bv = *reinterpret_cast<const float2*>(Bptr + k0);
        Bs[lb_k0][lb_n] = bv.x;
        Bs[lb_k0 + 1][lb_n] = bv.y;
        __syncthreads();
#pragma unroll
        for (int kk = 0; kk < 4; kk++) {
            ulonglong2 q0 = *reinterpret_cast<const ulonglong2*>(&Bs[kk][tx * 8]);
            ulonglong2 q1 = *reinterpret_cast<const ulonglong2*>(&Bs[kk][tx * 8 + 4]);
#pragma unroll
            for (int i = 0; i < 4; i++) {
                unsigned long long ad = dup2(As[ty * 4 + i][kk]);
                fma2(acc[i][0], ad, q0.x);
                fma2(acc[i][1], ad, q0.y);
                fma2(acc[i][2], ad, q1.x);
                fma2(acc[i][3], ad, q1.y);
            }
        }
        __syncthreads();
    }

    int nb = n0 + tx * 8;
#pragma unroll
    for (int i = 0; i < 4; i++) {
        float* crow = C + (size_t)(m0 + ty * 4 + i) * N + nb;
#pragma unroll
        for (int j = 0; j < 4; j++) {
            crow[j * 2] = lo32(acc[i][j]) * scale;
            crow[j * 2 + 1] = hi32(acc[i][j]) * scale;
        }
    }
}

// ---------------- BatchNorm ----------------
__global__ void zero_bn_kernel() {
    int c = threadIdx.x;
    if (c < EMBD) { g_bnsum[c] = 0.f; g_bnss[c] = 0.f; }
}

__global__ void bn_stats_kernel() {
    int c = threadIdx.x;  // blockDim.x == EMBD
    int r0 = blockIdx.x * 512;
    int r1 = min(r0 + 512, NNODES);
    float s = 0.f, ss = 0.f;
    for (int r = r0; r < r1; r++) {
        float v = g_h[(size_t)r * LDH + c];
        s += v;
        ss += v * v;
    }
    atomicAdd(&g_bnsum[c], s);
    atomicAdd(&g_bnss[c], ss);
}

__global__ void bn_finalize_kernel(const float* __restrict__ gamma,
                                   const float* __restrict__ beta) {
    int c = threadIdx.x;
    if (c >= EMBD) return;
    float mean = g_bnsum[c] * (1.0f / NNODES);
    float var = g_bnss[c] * (1.0f / NNODES) - mean * mean;
    float rs = rsqrtf(var + 1e-5f);
    float sc = rs * gamma[c];
    g_bnscale[c] = sc;
    g_bnshift[c] = beta[c] - mean * sc;
}

__global__ void bn_apply_kernel(int doRelu) {
    int idx = blockIdx.x * blockDim.x + threadIdx.x;
    if (idx >= NNODES * C4) return;
    int n = idx / C4, c = (idx % C4) * 4;
    float4 v = ld4(g_h + (size_t)n * LDH + c);
    float4 sc = ld4(g_bnscale + c);
    float4 sh = ld4(g_bnshift + c);
    v.x = fmaf(v.x, sc.x, sh.x);
    v.y = fmaf(v.y, sc.y, sh.y);
    v.z = fmaf(v.z, sc.z, sh.z);
    v.w = fmaf(v.w, sc.w, sh.w);
    if (doRelu) {
        v.x = fmaxf(v.x, 0.f); v.y = fmaxf(v.y, 0.f);
        v.z = fmaxf(v.z, 0.f); v.w = fmaxf(v.w, 0.f);
    }
    st4(g_h + (size_t)n * LDH + c, v);
}

// ---------------- pooling ----------------
__global__ void zero_pool_kernel() {
    int i = blockIdx.x * blockDim.x + threadIdx.x;
    if (i < NGRAPHS * LDH) g_pool[i] = 0.f;
    if (i < NGRAPHS) g_gcnt[i] = 0;
}

__global__ void gcount_kernel(const int* __restrict__ bi) {
    int n = blockIdx.x * blockDim.x + threadIdx.x;
    if (n < NNODES) atomicAdd(&g_gcnt[bi[n]], 1);
}

__global__ void pool_kernel(const int* __restrict__ bi) {
    int idx = blockIdx.x * blockDim.x + threadIdx.x;
    if (idx >= NNODES * C4) return;
    int n = idx / C4, c = (idx % C4) * 4;
    int g = bi[n];
    float4 v = ld4(g_h + (size_t)n * LDH + c);
    float* d = g_pool + (size_t)g * LDH + c;
    atomicAdd(d + 0, v.x);
    atomicAdd(d + 1, v.y);
    atomicAdd(d + 2, v.z);
    atomicAdd(d + 3, v.w);
}

__global__ void pool_div_kernel() {
    int i = blockIdx.x * blockDim.x + threadIdx.x;
    if (i >= NGRAPHS * LDH) return;
    int g = i / LDH;
    float cnt = fmaxf((float)g_gcnt[g], 1.0f);
    g_pool[i] /= cnt;
}

// ---------------- L2 row normalize ----------------
__global__ void normalize_kernel(float* __restrict__ f) {
    __shared__ float red[4];
    size_t r = blockIdx.x;
    float* row = f + r * LDH;
    float ss = 0.f;
    for (int c = threadIdx.x; c < EMBD; c += 128) {
        float v = row[c];
        ss += v * v;
    }
    for (int o = 16; o; o >>= 1) ss += __shfl_down_sync(0xffffffffu, ss, o);
    if ((threadIdx.x & 31) == 0) red[threadIdx.x >> 5] = ss;
    __syncthreads();
    if (threadIdx.x == 0) red[0] = rsqrtf(red[0] + red[1] + red[2] + red[3]);
    __syncthreads();
    float s = red[0];
    for (int c = threadIdx.x; c < EMBD; c += 128) row[c] *= s;
}

__global__ void labels_kernel(float* __restrict__ out, int extra) {
    int i = blockIdx.x * blockDim.x + threadIdx.x;
    if (i < extra) out[i] = (float)i;
}

// ---------------- host orchestration ----------------
extern "C" void kernel_launch(void* const* d_in, const int* in_sizes, int n_in,
                              void* d_out, int out_size) {
    const float* ae1 = (const float*)d_in[8];
    const float* ae2 = (const float*)d_in[9];
    const float* ee1 = (const float*)d_in[10];
    const float* ee2 = (const float*)d_in[11];
    const float* W1 = (const float*)d_in[12];
    const float* bm1 = (const float*)d_in[13];
    const float* W2 = (const float*)d_in[14];
    const float* bm2 = (const float*)d_in[15];
    const float* gamma = (const float*)d_in[16];
    const float* beta = (const float*)d_in[17];
    const float* Wp1 = (const float*)d_in[18];
    const float* bp1 = (const float*)d_in[19];
    const float* Wp2 = (const float*)d_in[20];
    const float* bp2 = (const float*)d_in[21];

    float *h, *pool, *feat;
    __nv_bfloat16 *ahi, *alo, *thi, *tlo, *whi, *wlo;
    cudaGetSymbolAddress((void**)&h, g_h);
    cudaGetSymbolAddress((void**)&pool, g_pool);
    cudaGetSymbolAddress((void**)&feat, g_feat);
    cudaGetSymbolAddress((void**)&ahi, g_ahi);
    cudaGetSymbolAddress((void**)&alo, g_alo);
    cudaGetSymbolAddress((void**)&thi, g_thi);
    cudaGetSymbolAddress((void**)&tlo, g_tlo);
    cudaGetSymbolAddress((void**)&whi, g_whi);
    cudaGetSymbolAddress((void**)&wlo, g_wlo);

    cudaFuncSetAttribute(mma_gemm<1, 1>, cudaFuncAttributeMaxDynamicSharedMemorySize,
                         GEMM_SMEM);
    cudaFuncSetAttribute(mma_gemm<0, 0>, cudaFuncAttributeMaxDynamicSharedMemorySize,
                         GEMM_SMEM);

    const int GN = (NNODES * C4 + 255) / 256;
    const int GN80 = (NNODES * 80 + 255) / 256;
    const int GE = (NEDGES + 255) / 256;
    const int GP = (NGRAPHS * LDH + 255) / 256;
    const int MT = MPAD / 128;  // 1563

    for (int enc = 0; enc < 2; enc++) {
        const int* x = (const int*)d_in[enc * 4 + 0];
        const int* ei = (const int*)d_in[enc * 4 + 1];
        const int* ea = (const int*)d_in[enc * 4 + 2];
        const int* bi = (const int*)d_in[enc * 4 + 3];

        zero_graphbufs_kernel<<<2048, 256>>>();
        edge_count_kernel<<<GE, 256>>>(ei, ea);
        scan_blocks_kernel<<<NBSCAN, 1024>>>();
        scan_sums_kernel<<<1, 32>>>();
        scan_add_kernel<<<NBSCAN, 1024>>>();
        fill_csr_kernel<<<GE, 256>>>(ei);

        init_h_kernel<<<GN, 256>>>(x, ae1, ae2);

        for (int l = 0; l < NLAYERS; l++) {
            agg_kernel<<<GN80, 256>>>(ee1 + l * 6 * EMBD, ee2 + l * 3 * EMBD);

            // GEMM1: [MPAD x 320] @ W1^T(split) -> t split bf16 [MPAD x 640], relu
            convert_w_kernel<<<(320 * 640 + 255) / 256, 256>>>(
                W1 + (size_t)l * EMBD * HID, EMBD, HID, 320, 640, whi, wlo);
            mma_gemm<1, 1><<<dim3(5, MT), 256, GEMM_SMEM>>>(
                ahi, alo, 320, 320, whi, wlo, 640, bm1 + l * HID,
                nullptr, thi, tlo, LDT, HID);

            // GEMM2: t [MPAD x 640] @ W2 -> h fp32 [MPAD x 320]
            convert_w_kernel<<<(640 * 320 + 255) / 256, 256>>>(
                W2 + (size_t)l * HID * EMBD, HID, EMBD, 640, 320, whi, wlo);
            mma_gemm<0, 0><<<dim3(3, MT), 256, GEMM_SMEM>>>(
                thi, tlo, LDT, 640, whi, wlo, 320, bm2 + l * EMBD,
                h, nullptr, nullptr, LDH, EMBD);

            zero_bn_kernel<<<1, 512>>>();
            bn_stats_kernel<<<(NNODES + 511) / 512, EMBD>>>();
            bn_finalize_kernel<<<1, 512>>>(gamma + l * EMBD, beta + l * EMBD);
            bn_apply_kernel<<<GN, 256>>>(l < NLAYERS - 1 ? 1 : 0);
        }

        zero_pool_kernel<<<GP, 256>>>();
        gcount_kernel<<<(NNODES + 255) / 256, 256>>>(bi);
        pool_kernel<<<GN, 256>>>(bi);
        pool_div_kernel<<<GP, 256>>>();

        // projection head (M=4096)
        convert_pool_kernel<<<GP, 256>>>(pool, ahi, alo);
        convert_w_kernel<<<(320 * 320 + 255) / 256, 256>>>(
            Wp1, EMBD, EMBD, 320, 320, whi, wlo);
        mma_gemm<1, 1><<<dim3(3, NGRAPHS / 128), 256, GEMM_SMEM>>>(
            ahi, alo, 320, 320, whi, wlo, 320, bp1,
            nullptr, thi, tlo, 320, EMBD);
        convert_w_kernel<<<(320 * 320 + 255) / 256, 256>>>(
            Wp2, EMBD, EMBD, 320, 320, whi, wlo);
        mma_gemm<0, 0><<<dim3(3, NGRAPHS / 128), 256, GEMM_SMEM>>>(
            thi, tlo, 320, 320, whi, wlo, 320, bp2,
            feat + (size_t)enc * NGRAPHS * LDH, nullptr, nullptr, LDH, EMBD);
    }

    normalize_kernel<<<2 * NGRAPHS, 128>>>(feat);

    gemm_nt_scale<<<dim3(NGRAPHS / 128, NGRAPHS / 64), 256>>>(
        feat, feat + (size_t)NGRAPHS * LDH, (float*)d_out,
        NGRAPHS, NGRAPHS, EMBD, LDH, TEMP_INV);

    long long logits_elems = (long long)NGRAPHS * NGRAPHS;
    int extra = (int)((long long)out_size - logits_elems);
    if (extra > 0)
        labels_kernel<<<(extra + 255) / 256, 256>>>(
            (float*)d_out + logits_elems, extra);
}

// round 5
// speedup vs baseline: 3.6280x; 1.0384x over previous
#include <cuda_runtime.h>
#include <cuda_bf16.h>
#include <math.h>
#include <stdint.h>

#define NNODES 200000
#define NEDGES 440000
#define NGRAPHS 4096
#define EMBD 300
#define HID 600
#define C4 75
#define NLAYERS 5
#define NBSCAN ((NNODES + 1 + 1023) / 1024)

#define LDH 320
#define LDT 640
#define MPAD 200064             // 1563 * 128

// ---------------- scratch ----------------
__device__ float g_h[MPAD * LDH];
__device__ __align__(16) __nv_bfloat16 g_ahi[(size_t)MPAD * LDH];
__device__ __align__(16) __nv_bfloat16 g_alo[(size_t)MPAD * LDH];
__device__ __align__(16) __nv_bfloat16 g_thi[(size_t)MPAD * LDT];
__device__ __align__(16) __nv_bfloat16 g_tlo[(size_t)MPAD * LDT];
__device__ __align__(16) __nv_bfloat16 g_whi[640 * 320];
__device__ __align__(16) __nv_bfloat16 g_wlo[640 * 320];
__device__ int   g_cnt[NNODES * 8];
__device__ int   g_rowptr[NNODES + 1];
__device__ int   g_cursor[NNODES + 2];
__device__ int   g_colidx[NEDGES];
__device__ int   g_bsums[256];
__device__ float g_bnsum[EMBD];
__device__ float g_bnss[EMBD];
__device__ float g_bnscale[EMBD];
__device__ float g_bnshift[EMBD];
__device__ float g_pool[NGRAPHS * LDH];
__device__ int   g_gcnt[NGRAPHS];
__device__ float g_feat[2 * NGRAPHS * LDH];

// ---------------- helpers ----------------
__device__ __forceinline__ float4 ld4(const float* p) {
    return *reinterpret_cast<const float4*>(p);
}
__device__ __forceinline__ void st4(float* p, float4 v) {
    *reinterpret_cast<float4*>(p) = v;
}
__device__ __forceinline__ float4 f4add(float4 a, float4 b) {
    return make_float4(a.x + b.x, a.y + b.y, a.z + b.z, a.w + b.w);
}
__device__ __forceinline__ float4 f4fma(float4 a, float s, float4 c) {
    return make_float4(fmaf(a.x, s, c.x), fmaf(a.y, s, c.y),
                       fmaf(a.z, s, c.z), fmaf(a.w, s, c.w));
}
__device__ __forceinline__ uint32_t smem_u32(const void* p) {
    uint32_t a;
    asm("{ .reg .u64 t; cvta.to.shared.u64 t, %1; cvt.u32.u64 %0, t; }"
        : "=r"(a) : "l"(p));
    return a;
}
__device__ __forceinline__ void cpasync16(uint32_t dst, const void* src) {
    asm volatile("cp.async.cg.shared.global [%0], [%1], 16;"
                 :: "r"(dst), "l"(src));
}

#define LDSM_X4(r0, r1, r2, r3, addr) \
    asm volatile("ldmatrix.sync.aligned.m8n8.x4.shared.b16 {%0,%1,%2,%3}, [%4];" \
                 : "=r"(r0), "=r"(r1), "=r"(r2), "=r"(r3) : "r"(addr))

#define MMA16816(c, a, b0, b1) \
    asm volatile("mma.sync.aligned.m16n8k16.row.col.f32.bf16.bf16.f32 " \
                 "{%0,%1,%2,%3}, {%4,%5,%6,%7}, {%8,%9}, {%0,%1,%2,%3};" \
                 : "+f"((c)[0]), "+f"((c)[1]), "+f"((c)[2]), "+f"((c)[3]) \
                 : "r"((a)[0]), "r"((a)[1]), "r"((a)[2]), "r"((a)[3]), \
                   "r"(b0), "r"(b1))

// smem stage: AH 16K | AL 16K | BH 32K | BL 32K = 96K per stage, 2 stages
#define SM_AH 0
#define SM_AL 16384
#define SM_BH 32768
#define SM_BL 65536
#define STAGE 98304
#define GEMM_SMEM (2 * STAGE)

// ---------------- weight convert: W[K,N] fp32 -> Bt[Npad,Kpad] bf16 hi/lo ----
__global__ void convert_w_kernel(const float* __restrict__ W, int Kreal, int Nreal,
                                 int Kpad, int Npad,
                                 __nv_bfloat16* __restrict__ hi,
                                 __nv_bfloat16* __restrict__ lo) {
    int idx = blockIdx.x * blockDim.x + threadIdx.x;
    if (idx >= Kpad * Npad) return;
    int n = idx / Kpad, k = idx % Kpad;
    float v = (k < Kreal && n < Nreal) ? W[k * Nreal + n] : 0.f;
    __nv_bfloat16 h = __float2bfloat16_rn(v);
    float r = v - __bfloat162float(h);
    hi[idx] = h;
    lo[idx] = __float2bfloat16_rn(r);
}

// generic fp32 -> split bf16 (same layout)
__global__ void convert_split_kernel(const float* __restrict__ src, int n,
                                     __nv_bfloat16* __restrict__ hi,
                                     __nv_bfloat16* __restrict__ lo) {
    int idx = blockIdx.x * blockDim.x + threadIdx.x;
    if (idx >= n) return;
    float v = src[idx];
    __nv_bfloat16 h = __float2bfloat16_rn(v);
    hi[idx] = h;
    lo[idx] = __float2bfloat16_rn(v - __bfloat162float(h));
}

// ---------------- stage loader (cp.async, SW128 swizzle), 128M x 256N -------
__device__ __forceinline__ void gemm_load_stage(
    uint32_t sbase, int tid, int m0, int n0, int k0,
    const __nv_bfloat16* Ahi, const __nv_bfloat16* Alo, int lda,
    const __nv_bfloat16* Bhi, const __nv_bfloat16* Blo, int Kpad, int Npad) {
#pragma unroll
    for (int it = 0; it < 4; it++) {
        int L = it * 256 + tid;       // 0..1023 -> 128 rows x 8 segs
        int row = L >> 3, j = L & 7;
        uint32_t soff = (uint32_t)row * 128 +
                        (((uint32_t)j * 16) ^ (((uint32_t)(row & 7)) << 4));
        size_t aoff = (size_t)(m0 + row) * lda + k0 + j * 8;
        cpasync16(sbase + SM_AH + soff, Ahi + aoff);
        cpasync16(sbase + SM_AL + soff, Alo + aoff);
    }
#pragma unroll
    for (int it = 0; it < 8; it++) {
        int L = it * 256 + tid;       // 0..2047 -> 256 rows x 8 segs
        int row = L >> 3, j = L & 7;
        uint32_t soff = (uint32_t)row * 128 +
                        (((uint32_t)j * 16) ^ (((uint32_t)(row & 7)) << 4));
        int brow = n0 + row;
        brow = brow < Npad ? brow : Npad - 1;
        size_t boff = (size_t)brow * Kpad + k0 + j * 8;
        cpasync16(sbase + SM_BH + soff, Bhi + boff);
        cpasync16(sbase + SM_BL + soff, Blo + boff);
    }
    asm volatile("cp.async.commit_group;" ::: "memory");
}

// ---------------- split-bf16 mma.sync GEMM, tile 128M x 256N -----------------
// C = op(A @ Bt^T + bias) * scale. A split bf16 [M x lda], Bt split [Npad x Kpad].
// Warp tile 64x64. grid = (ceil(ldc/256), M/128).
// STATS: accumulate per-column sum/sumsq over rows < NNODES into g_bnsum/g_bnss.
template <int RELU, int SPLITOUT, int STATS>
__global__ void __launch_bounds__(256, 1)
mma_gemm(const __nv_bfloat16* __restrict__ Ahi, const __nv_bfloat16* __restrict__ Alo,
         int lda, int Kpad,
         const __nv_bfloat16* __restrict__ Bhi, const __nv_bfloat16* __restrict__ Blo,
         int Npad, const float* __restrict__ bias, float scale,
         float* __restrict__ C, __nv_bfloat16* __restrict__ Chi,
         __nv_bfloat16* __restrict__ Clo, int ldc, int Nreal) {
    extern __shared__ char smem[];
    uint32_t sb = smem_u32(smem);
    int tid = threadIdx.x;
    int m0 = blockIdx.y * 128, n0 = blockIdx.x * 256;
    int n_tile = min(256, ldc - n0);
    int nchunks = Kpad >> 6;

    gemm_load_stage(sb, tid, m0, n0, 0, Ahi, Alo, lda, Bhi, Blo, Kpad, Npad);
    gemm_load_stage(sb + STAGE, tid, m0, n0, 64, Ahi, Alo, lda, Bhi, Blo, Kpad, Npad);

    int lane = tid & 31, wid = tid >> 5;
    int wm = wid & 1, wn = wid >> 1;
    bool wactive = (wn * 64 < n_tile);

    float acc[4][8][4];
#pragma unroll
    for (int i = 0; i < 4; i++)
#pragma unroll
        for (int j = 0; j < 8; j++)
#pragma unroll
            for (int r = 0; r < 4; r++) acc[i][j][r] = 0.f;

    uint32_t mask = ((uint32_t)(lane & 7)) << 4;
    uint32_t a_row_off[4];
#pragma unroll
    for (int i = 0; i < 4; i++)
        a_row_off[i] = (uint32_t)(wm * 64 + i * 16 + (lane & 15)) * 128;
    uint32_t a_kb_base = (uint32_t)((lane >> 4) * 16);
    int g = lane >> 3;
    uint32_t b_row_base = (uint32_t)(wn * 64 + (g >> 1) * 8 + (lane & 7));
    uint32_t b_kb_base = (uint32_t)((g & 1) * 16);

    for (int ch = 0; ch < nchunks; ch++) {
        asm volatile("cp.async.wait_group 1;" ::: "memory");
        __syncthreads();
        uint32_t st = sb + (uint32_t)(ch & 1) * STAGE;
#pragma unroll
        for (int s = 0; s < 4; s++) {
            uint32_t akb = (a_kb_base + s * 32) ^ mask;
            uint32_t bkb = (b_kb_base + s * 32) ^ mask;
            uint32_t ah[4][4], al[4][4];
#pragma unroll
            for (int i = 0; i < 4; i++) {
                LDSM_X4(ah[i][0], ah[i][1], ah[i][2], ah[i][3],
                        st + SM_AH + a_row_off[i] + akb);
                LDSM_X4(al[i][0], al[i][1], al[i][2], al[i][3],
                        st + SM_AL + a_row_off[i] + akb);
            }
            if (wactive) {
#pragma unroll
                for (int q = 0; q < 4; q++) {
                    uint32_t broff = (b_row_base + q * 16) * 128;
                    uint32_t bh[4], bl[4];
                    LDSM_X4(bh[0], bh[1], bh[2], bh[3], st + SM_BH + broff + bkb);
                    LDSM_X4(bl[0], bl[1], bl[2], bl[3], st + SM_BL + broff + bkb);
#pragma unroll
                    for (int i = 0; i < 4; i++) {
                        MMA16816(acc[i][2 * q], ah[i], bh[0], bh[1]);
                        MMA16816(acc[i][2 * q], ah[i], bl[0], bl[1]);
                        MMA16816(acc[i][2 * q], al[i], bh[0], bh[1]);
                        MMA16816(acc[i][2 * q + 1], ah[i], bh[2], bh[3]);
                        MMA16816(acc[i][2 * q + 1], ah[i], bl[2], bl[3]);
                        MMA16816(acc[i][2 * q + 1], al[i], bh[2], bh[3]);
                    }
                }
            }
        }
        __syncthreads();
        if (ch + 2 < nchunks)
            gemm_load_stage(st, tid, m0, n0, (ch + 2) * 64,
                            Ahi, Alo, lda, Bhi, Blo, Kpad, Npad);
        else
            asm volatile("cp.async.commit_group;" ::: "memory");
    }

    // ---- epilogue (+ optional column stats) ----
#pragma unroll
    for (int j = 0; j < 8; j++) {
        int col = n0 + wn * 64 + j * 8 + (lane & 3) * 2;
        float b0 = 0.f, b1 = 0.f;
        if (bias != nullptr) {
            b0 = (col < Nreal) ? bias[col] : 0.f;
            b1 = (col + 1 < Nreal) ? bias[col + 1] : 0.f;
        }
        float s0 = 0.f, s1 = 0.f, q0 = 0.f, q1 = 0.f;
#pragma unroll
        for (int i = 0; i < 4; i++) {
            int r0 = m0 + wm * 64 + i * 16 + (lane >> 2);
            float v00 = (col < Nreal) ? (acc[i][j][0] + b0) * scale : 0.f;
            float v01 = (col + 1 < Nreal) ? (acc[i][j][1] + b1) * scale : 0.f;
            float v10 = (col < Nreal) ? (acc[i][j][2] + b0) * scale : 0.f;
            float v11 = (col + 1 < Nreal) ? (acc[i][j][3] + b1) * scale : 0.f;
            if (RELU) {
                v00 = fmaxf(v00, 0.f); v01 = fmaxf(v01, 0.f);
                v10 = fmaxf(v10, 0.f); v11 = fmaxf(v11, 0.f);
            }
            if (STATS) {
                bool ok0 = (r0 < NNODES), ok1 = (r0 + 8 < NNODES);
                s0 += (ok0 ? v00 : 0.f) + (ok1 ? v10 : 0.f);
                s1 += (ok0 ? v01 : 0.f) + (ok1 ? v11 : 0.f);
                q0 += (ok0 ? v00 * v00 : 0.f) + (ok1 ? v10 * v10 : 0.f);
                q1 += (ok0 ? v01 * v01 : 0.f) + (ok1 ? v11 * v11 : 0.f);
            }
            if (col < ldc) {
                if (SPLITOUT) {
                    __nv_bfloat16 h00 = __float2bfloat16_rn(v00);
                    __nv_bfloat16 h01 = __float2bfloat16_rn(v01);
                    __nv_bfloat16 h10 = __float2bfloat16_rn(v10);
                    __nv_bfloat16 h11 = __float2bfloat16_rn(v11);
                    __nv_bfloat162 hh0; hh0.x = h00; hh0.y = h01;
                    __nv_bfloat162 hh1; hh1.x = h10; hh1.y = h11;
                    __nv_bfloat162 ll0;
                    ll0.x = __float2bfloat16_rn(v00 - __bfloat162float(h00));
                    ll0.y = __float2bfloat16_rn(v01 - __bfloat162float(h01));
                    __nv_bfloat162 ll1;
                    ll1.x = __float2bfloat16_rn(v10 - __bfloat162float(h10));
                    ll1.y = __float2bfloat16_rn(v11 - __bfloat162float(h11));
                    *reinterpret_cast<__nv_bfloat162*>(Chi + (size_t)r0 * ldc + col) = hh0;
                    *reinterpret_cast<__nv_bfloat162*>(Clo + (size_t)r0 * ldc + col) = ll0;
                    *reinterpret_cast<__nv_bfloat162*>(Chi + (size_t)(r0 + 8) * ldc + col) = hh1;
                    *reinterpret_cast<__nv_bfloat162*>(Clo + (size_t)(r0 + 8) * ldc + col) = ll1;
                } else {
                    *reinterpret_cast<float2*>(C + (size_t)r0 * ldc + col) =
                        make_float2(v00, v01);
                    *reinterpret_cast<float2*>(C + (size_t)(r0 + 8) * ldc + col) =
                        make_float2(v10, v11);
                }
            }
        }
        if (STATS) {
#pragma unroll
            for (int o = 16; o >= 4; o >>= 1) {
                s0 += __shfl_down_sync(0xffffffffu, s0, o);
                s1 += __shfl_down_sync(0xffffffffu, s1, o);
                q0 += __shfl_down_sync(0xffffffffu, q0, o);
                q1 += __shfl_down_sync(0xffffffffu, q1, o);
            }
            if (lane < 4 && col < Nreal) {
                atomicAdd(&g_bnsum[col], s0);
                atomicAdd(&g_bnsum[col + 1], s1);
                atomicAdd(&g_bnss[col], q0);
                atomicAdd(&g_bnss[col + 1], q1);
            }
        }
    }
}

// ---------------- graph structure ----------------
__global__ void zero_graphbufs_kernel() {
    int i = blockIdx.x * blockDim.x + threadIdx.x;
    int stride = gridDim.x * blockDim.x;
    for (int j = i; j < NNODES * 8; j += stride) g_cnt[j] = 0;
    for (int j = i; j <= NNODES; j += stride) g_cursor[j] = 0;
}

__global__ void edge_count_kernel(const int* __restrict__ ei,
                                  const int* __restrict__ ea) {
    int e = blockIdx.x * blockDim.x + threadIdx.x;
    if (e >= NEDGES) return;
    int dst = ei[NEDGES + e];
    atomicAdd(&g_cursor[dst], 1);
    atomicAdd(&g_cnt[dst * 8 + (ea[2 * e] & 3)], 1);
    atomicAdd(&g_cnt[dst * 8 + 4 + (ea[2 * e + 1] & 3)], 1);
}

__global__ void scan_blocks_kernel() {
    __shared__ int s[1024];
    int tid = threadIdx.x;
    int gid = blockIdx.x * 1024 + tid;
    int v = (gid <= NNODES) ? g_cursor[gid] : 0;
    s[tid] = v;
    __syncthreads();
    for (int off = 1; off < 1024; off <<= 1) {
        int t = (tid >= off) ? s[tid - off] : 0;
        __syncthreads();
        s[tid] += t;
        __syncthreads();
    }
    if (gid <= NNODES) g_rowptr[gid] = s[tid] - v;
    if (tid == 1023) g_bsums[blockIdx.x] = s[1023];
}

__global__ void scan_sums_kernel() {
    if (threadIdx.x == 0) {
        int acc = 0;
        for (int i = 0; i < NBSCAN; i++) {
            int t = g_bsums[i];
            g_bsums[i] = acc;
            acc += t;
        }
    }
}

__global__ void scan_add_kernel() {
    int gid = blockIdx.x * 1024 + threadIdx.x;
    if (gid <= NNODES) {
        int v = g_rowptr[gid] + g_bsums[blockIdx.x];
        g_rowptr[gid] = v;
        g_cursor[gid] = v;
    }
}

__global__ void fill_csr_kernel(const int* __restrict__ ei) {
    int e = blockIdx.x * blockDim.x + threadIdx.x;
    if (e >= NEDGES) return;
    int dst = ei[NEDGES + e];
    int pos = atomicAdd(&g_cursor[dst], 1);
    g_colidx[pos] = ei[e];
}

// ---------------- features ----------------
__global__ void init_h_kernel(const int* __restrict__ x,
                              const float* __restrict__ ae1,
                              const float* __restrict__ ae2) {
    int idx = blockIdx.x * blockDim.x + threadIdx.x;
    if (idx >= NNODES * C4) return;
    int n = idx / C4, c = (idx % C4) * 4;
    float4 v = f4add(ld4(ae1 + x[2 * n] * EMBD + c),
                     ld4(ae2 + x[2 * n + 1] * EMBD + c));
    st4(g_h + (size_t)n * LDH + c, v);
}

// agg -> split bf16 directly (GEMM1 input). BN template: apply relu(h*sc+sh)
// to every gathered h value (h stored raw; BN params from previous layer).
template <int BN>
__global__ void agg_kernel(const float* __restrict__ ee1,
                           const float* __restrict__ ee2) {
    int idx = blockIdx.x * blockDim.x + threadIdx.x;
    if (idx >= NNODES * 80) return;
    int n = idx / 80, c4 = idx % 80;
    int c = c4 * 4;
    size_t o = (size_t)n * LDH + c;
    if (c4 >= C4) {
        *reinterpret_cast<uint2*>(&g_ahi[o]) = make_uint2(0u, 0u);
        *reinterpret_cast<uint2*>(&g_alo[o]) = make_uint2(0u, 0u);
        return;
    }
    float4 sc, sh;
    if (BN) { sc = ld4(g_bnscale + c); sh = ld4(g_bnshift + c); }
    auto xf = [&](float4 v) -> float4 {
        if (BN) {
            v.x = fmaxf(fmaf(v.x, sc.x, sh.x), 0.f);
            v.y = fmaxf(fmaf(v.y, sc.y, sh.y), 0.f);
            v.z = fmaxf(fmaf(v.z, sc.z, sh.z), 0.f);
            v.w = fmaxf(fmaf(v.w, sc.w, sh.w), 0.f);
        }
        return v;
    };
    float4 acc = xf(ld4(g_h + o));  // self message
    int base = n * 8;
    float c00 = (float)g_cnt[base + 0];
    float c01 = (float)g_cnt[base + 1];
    float c02 = (float)g_cnt[base + 2];
    float c10 = (float)g_cnt[base + 4] + 1.0f;
    float c11 = (float)g_cnt[base + 5];
    float c12 = (float)g_cnt[base + 6];
    acc = f4fma(ld4(ee1 + 0 * EMBD + c), c00, acc);
    acc = f4fma(ld4(ee1 + 1 * EMBD + c), c01, acc);
    acc = f4fma(ld4(ee1 + 2 * EMBD + c), c02, acc);
    acc = f4add(acc, ld4(ee1 + 4 * EMBD + c));
    acc = f4fma(ld4(ee2 + 0 * EMBD + c), c10, acc);
    acc = f4fma(ld4(ee2 + 1 * EMBD + c), c11, acc);
    acc = f4fma(ld4(ee2 + 2 * EMBD + c), c12, acc);
    int rs = g_rowptr[n], re = g_rowptr[n + 1];
    for (int i = rs; i < re; i++) {
        int s = g_colidx[i];
        acc = f4add(acc, xf(ld4(g_h + (size_t)s * LDH + c)));
    }
    __nv_bfloat162 h01 = __floats2bfloat162_rn(acc.x, acc.y);
    __nv_bfloat162 h23 = __floats2bfloat162_rn(acc.z, acc.w);
    __nv_bfloat162 l01 = __floats2bfloat162_rn(acc.x - __bfloat162float(h01.x),
                                               acc.y - __bfloat162float(h01.y));
    __nv_bfloat162 l23 = __floats2bfloat162_rn(acc.z - __bfloat162float(h23.x),
                                               acc.w - __bfloat162float(h23.y));
    *reinterpret_cast<uint2*>(&g_ahi[o]) =
        make_uint2(*reinterpret_cast<uint32_t*>(&h01),
                   *reinterpret_cast<uint32_t*>(&h23));
    *reinterpret_cast<uint2*>(&g_alo[o]) =
        make_uint2(*reinterpret_cast<uint32_t*>(&l01),
                   *reinterpret_cast<uint32_t*>(&l23));
}

// ---------------- BatchNorm (stats come from GEMM2 epilogue) ----------------
__global__ void zero_bn_kernel() {
    int c = threadIdx.x;
    if (c < EMBD) { g_bnsum[c] = 0.f; g_bnss[c] = 0.f; }
}

__global__ void bn_finalize_kernel(const float* __restrict__ gamma,
                                   const float* __restrict__ beta) {
    int c = threadIdx.x;
    if (c >= EMBD) return;
    float mean = g_bnsum[c] * (1.0f / NNODES);
    float var = g_bnss[c] * (1.0f / NNODES) - mean * mean;
    float rs = rsqrtf(var + 1e-5f);
    float s = rs * gamma[c];
    g_bnscale[c] = s;
    g_bnshift[c] = beta[c] - mean * s;
}

// ---------------- pooling (BN of last layer folded into pool_div) ----------
__global__ void zero_pool_kernel() {
    int i = blockIdx.x * blockDim.x + threadIdx.x;
    if (i < NGRAPHS * LDH) g_pool[i] = 0.f;
    if (i < NGRAPHS) g_gcnt[i] = 0;
}

__global__ void gcount_kernel(const int* __restrict__ bi) {
    int n = blockIdx.x * blockDim.x + threadIdx.x;
    if (n < NNODES) atomicAdd(&g_gcnt[bi[n]], 1);
}

__global__ void pool_kernel(const int* __restrict__ bi) {
    int idx = blockIdx.x * blockDim.x + threadIdx.x;
    if (idx >= NNODES * C4) return;
    int n = idx / C4, c = (idx % C4) * 4;
    int g = bi[n];
    float4 v = ld4(g_h + (size_t)n * LDH + c);
    float* d = g_pool + (size_t)g * LDH + c;
    atomicAdd(d + 0, v.x);
    atomicAdd(d + 1, v.y);
    atomicAdd(d + 2, v.z);
    atomicAdd(d + 3, v.w);
}

__global__ void pool_div_kernel() {
    int i = blockIdx.x * blockDim.x + threadIdx.x;
    if (i >= NGRAPHS * LDH) return;
    int g = i / LDH, c = i % LDH;
    if (c >= EMBD) { g_pool[i] = 0.f; return; }
    float cnt = fmaxf((float)g_gcnt[g], 1.0f);
    g_pool[i] = fmaf(g_pool[i] / cnt, g_bnscale[c], g_bnshift[c]);
}

// ---------------- L2 row normalize ----------------
__global__ void normalize_kernel(float* __restrict__ f) {
    __shared__ float red[4];
    size_t r = blockIdx.x;
    float* row = f + r * LDH;
    float ss = 0.f;
    for (int c = threadIdx.x; c < EMBD; c += 128) {
        float v = row[c];
        ss += v * v;
    }
    for (int o = 16; o; o >>= 1) ss += __shfl_down_sync(0xffffffffu, ss, o);
    if ((threadIdx.x & 31) == 0) red[threadIdx.x >> 5] = ss;
    __syncthreads();
    if (threadIdx.x == 0) red[0] = rsqrtf(red[0] + red[1] + red[2] + red[3]);
    __syncthreads();
    float s = red[0];
    for (int c = threadIdx.x; c < EMBD; c += 128) row[c] *= s;
}

__global__ void labels_kernel(float* __restrict__ out, int extra) {
    int i = blockIdx.x * blockDim.x + threadIdx.x;
    if (i < extra) out[i] = (float)i;
}

// ---------------- host orchestration ----------------
extern "C" void kernel_launch(void* const* d_in, const int* in_sizes, int n_in,
                              void* d_out, int out_size) {
    const float* ae1 = (const float*)d_in[8];
    const float* ae2 = (const float*)d_in[9];
    const float* ee1 = (const float*)d_in[10];
    const float* ee2 = (const float*)d_in[11];
    const float* W1 = (const float*)d_in[12];
    const float* bm1 = (const float*)d_in[13];
    const float* W2 = (const float*)d_in[14];
    const float* bm2 = (const float*)d_in[15];
    const float* gamma = (const float*)d_in[16];
    const float* beta = (const float*)d_in[17];
    const float* Wp1 = (const float*)d_in[18];
    const float* bp1 = (const float*)d_in[19];
    const float* Wp2 = (const float*)d_in[20];
    const float* bp2 = (const float*)d_in[21];

    float *h, *pool, *feat;
    __nv_bfloat16 *ahi, *alo, *thi, *tlo, *whi, *wlo;
    cudaGetSymbolAddress((void**)&h, g_h);
    cudaGetSymbolAddress((void**)&pool, g_pool);
    cudaGetSymbolAddress((void**)&feat, g_feat);
    cudaGetSymbolAddress((void**)&ahi, g_ahi);
    cudaGetSymbolAddress((void**)&alo, g_alo);
    cudaGetSymbolAddress((void**)&thi, g_thi);
    cudaGetSymbolAddress((void**)&tlo, g_tlo);
    cudaGetSymbolAddress((void**)&whi, g_whi);
    cudaGetSymbolAddress((void**)&wlo, g_wlo);

    cudaFuncSetAttribute(mma_gemm<1, 1, 0>,
                         cudaFuncAttributeMaxDynamicSharedMemorySize, GEMM_SMEM);
    cudaFuncSetAttribute(mma_gemm<0, 0, 1>,
                         cudaFuncAttributeMaxDynamicSharedMemorySize, GEMM_SMEM);
    cudaFuncSetAttribute(mma_gemm<0, 0, 0>,
                         cudaFuncAttributeMaxDynamicSharedMemorySize, GEMM_SMEM);

    const int GN = (NNODES * C4 + 255) / 256;
    const int GN80 = (NNODES * 80 + 255) / 256;
    const int GE = (NEDGES + 255) / 256;
    const int GP = (NGRAPHS * LDH + 255) / 256;
    const int MT = MPAD / 128;  // 1563

    for (int enc = 0; enc < 2; enc++) {
        const int* x = (const int*)d_in[enc * 4 + 0];
        const int* ei = (const int*)d_in[enc * 4 + 1];
        const int* ea = (const int*)d_in[enc * 4 + 2];
        const int* bi = (const int*)d_in[enc * 4 + 3];

        zero_graphbufs_kernel<<<2048, 256>>>();
        edge_count_kernel<<<GE, 256>>>(ei, ea);
        scan_blocks_kernel<<<NBSCAN, 1024>>>();
        scan_sums_kernel<<<1, 32>>>();
        scan_add_kernel<<<NBSCAN, 1024>>>();
        fill_csr_kernel<<<GE, 256>>>(ei);

        init_h_kernel<<<GN, 256>>>(x, ae1, ae2);

        for (int l = 0; l < NLAYERS; l++) {
            if (l == 0)
                agg_kernel<0><<<GN80, 256>>>(ee1 + l * 6 * EMBD, ee2 + l * 3 * EMBD);
            else
                agg_kernel<1><<<GN80, 256>>>(ee1 + l * 6 * EMBD, ee2 + l * 3 * EMBD);

            // GEMM1: agg(split) @ W1 -> t split bf16 [MPAD x 640], relu
            convert_w_kernel<<<(320 * 640 + 255) / 256, 256>>>(
                W1 + (size_t)l * EMBD * HID, EMBD, HID, 320, 640, whi, wlo);
            mma_gemm<1, 1, 0><<<dim3(3, MT), 256, GEMM_SMEM>>>(
                ahi, alo, 320, 320, whi, wlo, 640, bm1 + l * HID, 1.0f,
                nullptr, thi, tlo, LDT, HID);

            // GEMM2: t(split) @ W2 -> h fp32 [MPAD x 320], + column stats
            convert_w_kernel<<<(640 * 320 + 255) / 256, 256>>>(
                W2 + (size_t)l * HID * EMBD, HID, EMBD, 640, 320, whi, wlo);
            zero_bn_kernel<<<1, 512>>>();
            mma_gemm<0, 0, 1><<<dim3(2, MT), 256, GEMM_SMEM>>>(
                thi, tlo, LDT, 640, whi, wlo, 320, bm2 + l * EMBD, 1.0f,
                h, nullptr, nullptr, LDH, EMBD);
            bn_finalize_kernel<<<1, 512>>>(gamma + l * EMBD, beta + l * EMBD);
        }

        // mean pool of BN(h_last): accumulate raw h, fold BN into the divide
        zero_pool_kernel<<<GP, 256>>>();
        gcount_kernel<<<(NNODES + 255) / 256, 256>>>(bi);
        pool_kernel<<<GN, 256>>>(bi);
        pool_div_kernel<<<GP, 256>>>();

        // projection head (M=4096)
        convert_split_kernel<<<GP, 256>>>(pool, NGRAPHS * LDH, ahi, alo);
        convert_w_kernel<<<(320 * 320 + 255) / 256, 256>>>(
            Wp1, EMBD, EMBD, 320, 320, whi, wlo);
        mma_gemm<1, 1, 0><<<dim3(2, NGRAPHS / 128), 256, GEMM_SMEM>>>(
            ahi, alo, 320, 320, whi, wlo, 320, bp1, 1.0f,
            nullptr, thi, tlo, 320, EMBD);
        convert_w_kernel<<<(320 * 320 + 255) / 256, 256>>>(
            Wp2, EMBD, EMBD, 320, 320, whi, wlo);
        mma_gemm<0, 0, 0><<<dim3(2, NGRAPHS / 128), 256, GEMM_SMEM>>>(
            thi, tlo, 320, 320, whi, wlo, 320, bp2, 1.0f,
            feat + (size_t)enc * NGRAPHS * LDH, nullptr, nullptr, LDH, EMBD);
    }

    normalize_kernel<<<2 * NGRAPHS, 128>>>(feat);

    // logits = 25 * f0 @ f1^T via the same split-bf16 HMMA GEMM
    convert_split_kernel<<<(2 * NGRAPHS * LDH + 255) / 256, 256>>>(
        feat, 2 * NGRAPHS * LDH, ahi, alo);
    mma_gemm<0, 0, 0><<<dim3(NGRAPHS / 256, NGRAPHS / 128), 256, GEMM_SMEM>>>(
        ahi, alo, 320, 320,
        ahi + (size_t)NGRAPHS * LDH, alo + (size_t)NGRAPHS * LDH, NGRAPHS,
        nullptr, 25.0f, (float*)d_out, nullptr, nullptr, NGRAPHS, NGRAPHS);

    long long logits_elems = (long long)NGRAPHS * NGRAPHS;
    int extra = (int)((long long)out_size - logits_elems);
    if (extra > 0)
        labels_kernel<<<(extra + 255) / 256, 256>>>(
            (float*)d_out + logits_elems, extra);
}

// round 6
// speedup vs baseline: 4.4827x; 1.2356x over previous
#include <cuda_runtime.h>
#include <cuda_fp16.h>
#include <math.h>
#include <stdint.h>

#define NNODES 200000
#define NEDGES 440000
#define NGRAPHS 4096
#define EMBD 300
#define HID 600
#define C4 75
#define NLAYERS 5
#define NBSCAN ((NNODES + 1 + 1023) / 1024)

#define LDH 320
#define LDT 640
#define MPAD 200064             // 1563 * 128

// ---------------- scratch ----------------
__device__ float g_h[MPAD * LDH];
__device__ __align__(16) __half g_ahi[(size_t)MPAD * LDH];
__device__ __align__(16) __half g_alo[(size_t)MPAD * LDH];
__device__ __align__(16) __half g_thi[(size_t)MPAD * LDT];
__device__ __align__(16) __half g_tlo[(size_t)MPAD * LDT];
__device__ __align__(16) __half g_whi[640 * 320];
__device__ int   g_cnt[NNODES * 8];
__device__ int   g_rowptr[NNODES + 1];
__device__ int   g_cursor[NNODES + 2];
__device__ int   g_colidx[NEDGES];
__device__ int   g_bsums[256];
__device__ float g_bnsum[EMBD];
__device__ float g_bnss[EMBD];
__device__ float g_bnscale[EMBD];
__device__ float g_bnshift[EMBD];
__device__ float g_pool[NGRAPHS * LDH];
__device__ int   g_gcnt[NGRAPHS];
__device__ float g_feat[2 * NGRAPHS * LDH];

// ---------------- helpers ----------------
__device__ __forceinline__ float4 ld4(const float* p) {
    return *reinterpret_cast<const float4*>(p);
}
__device__ __forceinline__ void st4(float* p, float4 v) {
    *reinterpret_cast<float4*>(p) = v;
}
__device__ __forceinline__ float4 f4add(float4 a, float4 b) {
    return make_float4(a.x + b.x, a.y + b.y, a.z + b.z, a.w + b.w);
}
__device__ __forceinline__ float4 f4fma(float4 a, float s, float4 c) {
    return make_float4(fmaf(a.x, s, c.x), fmaf(a.y, s, c.y),
                       fmaf(a.z, s, c.z), fmaf(a.w, s, c.w));
}
__device__ __forceinline__ uint32_t smem_u32(const void* p) {
    uint32_t a;
    asm("{ .reg .u64 t; cvta.to.shared.u64 t, %1; cvt.u32.u64 %0, t; }"
        : "=r"(a) : "l"(p));
    return a;
}
__device__ __forceinline__ void cpasync16(uint32_t dst, const void* src) {
    asm volatile("cp.async.cg.shared.global [%0], [%1], 16;"
                 :: "r"(dst), "l"(src));
}

#define LDSM_X4(r0, r1, r2, r3, addr) \
    asm volatile("ldmatrix.sync.aligned.m8n8.x4.shared.b16 {%0,%1,%2,%3}, [%4];" \
                 : "=r"(r0), "=r"(r1), "=r"(r2), "=r"(r3) : "r"(addr))

#define MMA16816(c, a, b0, b1) \
    asm volatile("mma.sync.aligned.m16n8k16.row.col.f32.f16.f16.f32 " \
                 "{%0,%1,%2,%3}, {%4,%5,%6,%7}, {%8,%9}, {%0,%1,%2,%3};" \
                 : "+f"((c)[0]), "+f"((c)[1]), "+f"((c)[2]), "+f"((c)[3]) \
                 : "r"((a)[0]), "r"((a)[1]), "r"((a)[2]), "r"((a)[3]), \
                   "r"(b0), "r"(b1))

// smem stage: AH 16K | AL 16K | BH 32K = 64K per stage, 2 stages = 128K
#define SM_AH 0
#define SM_AL 16384
#define SM_BH 32768
#define STAGE 65536
#define GEMM_SMEM (2 * STAGE)

// ---------------- weight convert: W[K,N] fp32 -> Bt[Npad,Kpad] fp16 ---------
__global__ void convert_w_kernel(const float* __restrict__ W, int Kreal, int Nreal,
                                 int Kpad, int Npad, __half* __restrict__ hi) {
    int idx = blockIdx.x * blockDim.x + threadIdx.x;
    if (idx >= Kpad * Npad) return;
    int n = idx / Kpad, k = idx % Kpad;
    float v = (k < Kreal && n < Nreal) ? W[k * Nreal + n] : 0.f;
    hi[idx] = __float2half_rn(v);
}

// generic fp32 -> split fp16
__global__ void convert_split_kernel(const float* __restrict__ src, int n,
                                     __half* __restrict__ hi,
                                     __half* __restrict__ lo) {
    int idx = blockIdx.x * blockDim.x + threadIdx.x;
    if (idx >= n) return;
    float v = src[idx];
    __half h = __float2half_rn(v);
    hi[idx] = h;
    lo[idx] = __float2half_rn(v - __half2float(h));
}

// fp32 -> single fp16 (B operand of logits GEMM)
__global__ void convert_h_kernel(const float* __restrict__ src, int n,
                                 __half* __restrict__ hi) {
    int idx = blockIdx.x * blockDim.x + threadIdx.x;
    if (idx >= n) return;
    hi[idx] = __float2half_rn(src[idx]);
}

// ---------------- stage loader (cp.async, SW128 swizzle), 128M x 256N -------
__device__ __forceinline__ void gemm_load_stage(
    uint32_t sbase, int tid, int m0, int n0, int k0,
    const __half* Ahi, const __half* Alo, int lda,
    const __half* Bh, int Kpad, int Npad) {
#pragma unroll
    for (int it = 0; it < 4; it++) {
        int L = it * 256 + tid;       // 0..1023 -> 128 rows x 8 segs
        int row = L >> 3, j = L & 7;
        uint32_t soff = (uint32_t)row * 128 +
                        (((uint32_t)j * 16) ^ (((uint32_t)(row & 7)) << 4));
        size_t aoff = (size_t)(m0 + row) * lda + k0 + j * 8;
        cpasync16(sbase + SM_AH + soff, Ahi + aoff);
        cpasync16(sbase + SM_AL + soff, Alo + aoff);
    }
#pragma unroll
    for (int it = 0; it < 8; it++) {
        int L = it * 256 + tid;       // 0..2047 -> 256 rows x 8 segs
        int row = L >> 3, j = L & 7;
        uint32_t soff = (uint32_t)row * 128 +
                        (((uint32_t)j * 16) ^ (((uint32_t)(row & 7)) << 4));
        int brow = n0 + row;
        brow = brow < Npad ? brow : Npad - 1;
        size_t boff = (size_t)brow * Kpad + k0 + j * 8;
        cpasync16(sbase + SM_BH + soff, Bh + boff);
    }
    asm volatile("cp.async.commit_group;" ::: "memory");
}

// ---------------- 2-term split-fp16 mma.sync GEMM, tile 128M x 256N ---------
// C = op(A @ Bt^T + bias) * scale. A split fp16 (hi+lo), Bt single fp16.
// Warp tile 64x64. grid = (ceil(ldc/256), M/128).
template <int RELU, int SPLITOUT, int STATS>
__global__ void __launch_bounds__(256, 1)
mma_gemm(const __half* __restrict__ Ahi, const __half* __restrict__ Alo,
         int lda, int Kpad,
         const __half* __restrict__ Bh, int Npad,
         const float* __restrict__ bias, float scale,
         float* __restrict__ C, __half* __restrict__ Chi,
         __half* __restrict__ Clo, int ldc, int Nreal) {
    extern __shared__ char smem[];
    uint32_t sb = smem_u32(smem);
    int tid = threadIdx.x;
    int m0 = blockIdx.y * 128, n0 = blockIdx.x * 256;
    int n_tile = min(256, ldc - n0);
    int nchunks = Kpad >> 6;

    gemm_load_stage(sb, tid, m0, n0, 0, Ahi, Alo, lda, Bh, Kpad, Npad);
    gemm_load_stage(sb + STAGE, tid, m0, n0, 64, Ahi, Alo, lda, Bh, Kpad, Npad);

    int lane = tid & 31, wid = tid >> 5;
    int wm = wid & 1, wn = wid >> 1;
    bool wactive = (wn * 64 < n_tile);

    float acc[4][8][4];
#pragma unroll
    for (int i = 0; i < 4; i++)
#pragma unroll
        for (int j = 0; j < 8; j++)
#pragma unroll
            for (int r = 0; r < 4; r++) acc[i][j][r] = 0.f;

    uint32_t mask = ((uint32_t)(lane & 7)) << 4;
    uint32_t a_row_off[4];
#pragma unroll
    for (int i = 0; i < 4; i++)
        a_row_off[i] = (uint32_t)(wm * 64 + i * 16 + (lane & 15)) * 128;
    uint32_t a_kb_base = (uint32_t)((lane >> 4) * 16);
    int g = lane >> 3;
    uint32_t b_row_base = (uint32_t)(wn * 64 + (g >> 1) * 8 + (lane & 7));
    uint32_t b_kb_base = (uint32_t)((g & 1) * 16);

    for (int ch = 0; ch < nchunks; ch++) {
        asm volatile("cp.async.wait_group 1;" ::: "memory");
        __syncthreads();
        uint32_t st = sb + (uint32_t)(ch & 1) * STAGE;
#pragma unroll
        for (int s = 0; s < 4; s++) {
            uint32_t akb = (a_kb_base + s * 32) ^ mask;
            uint32_t bkb = (b_kb_base + s * 32) ^ mask;
            uint32_t ah[4][4], al[4][4];
#pragma unroll
            for (int i = 0; i < 4; i++) {
                LDSM_X4(ah[i][0], ah[i][1], ah[i][2], ah[i][3],
                        st + SM_AH + a_row_off[i] + akb);
                LDSM_X4(al[i][0], al[i][1], al[i][2], al[i][3],
                        st + SM_AL + a_row_off[i] + akb);
            }
            if (wactive) {
#pragma unroll
                for (int q = 0; q < 4; q++) {
                    uint32_t broff = (b_row_base + q * 16) * 128;
                    uint32_t bh[4];
                    LDSM_X4(bh[0], bh[1], bh[2], bh[3], st + SM_BH + broff + bkb);
#pragma unroll
                    for (int i = 0; i < 4; i++) {
                        MMA16816(acc[i][2 * q], ah[i], bh[0], bh[1]);
                        MMA16816(acc[i][2 * q], al[i], bh[0], bh[1]);
                        MMA16816(acc[i][2 * q + 1], ah[i], bh[2], bh[3]);
                        MMA16816(acc[i][2 * q + 1], al[i], bh[2], bh[3]);
                    }
                }
            }
        }
        __syncthreads();
        if (ch + 2 < nchunks)
            gemm_load_stage(st, tid, m0, n0, (ch + 2) * 64,
                            Ahi, Alo, lda, Bh, Kpad, Npad);
        else
            asm volatile("cp.async.commit_group;" ::: "memory");
    }

    // ---- epilogue (+ optional column stats) ----
#pragma unroll
    for (int j = 0; j < 8; j++) {
        int col = n0 + wn * 64 + j * 8 + (lane & 3) * 2;
        float b0 = 0.f, b1 = 0.f;
        if (bias != nullptr) {
            b0 = (col < Nreal) ? bias[col] : 0.f;
            b1 = (col + 1 < Nreal) ? bias[col + 1] : 0.f;
        }
        float s0 = 0.f, s1 = 0.f, q0 = 0.f, q1 = 0.f;
#pragma unroll
        for (int i = 0; i < 4; i++) {
            int r0 = m0 + wm * 64 + i * 16 + (lane >> 2);
            float v00 = (col < Nreal) ? (acc[i][j][0] + b0) * scale : 0.f;
            float v01 = (col + 1 < Nreal) ? (acc[i][j][1] + b1) * scale : 0.f;
            float v10 = (col < Nreal) ? (acc[i][j][2] + b0) * scale : 0.f;
            float v11 = (col + 1 < Nreal) ? (acc[i][j][3] + b1) * scale : 0.f;
            if (RELU) {
                v00 = fmaxf(v00, 0.f); v01 = fmaxf(v01, 0.f);
                v10 = fmaxf(v10, 0.f); v11 = fmaxf(v11, 0.f);
            }
            if (STATS) {
                bool ok0 = (r0 < NNODES), ok1 = (r0 + 8 < NNODES);
                s0 += (ok0 ? v00 : 0.f) + (ok1 ? v10 : 0.f);
                s1 += (ok0 ? v01 : 0.f) + (ok1 ? v11 : 0.f);
                q0 += (ok0 ? v00 * v00 : 0.f) + (ok1 ? v10 * v10 : 0.f);
                q1 += (ok0 ? v01 * v01 : 0.f) + (ok1 ? v11 * v11 : 0.f);
            }
            if (col < ldc) {
                if (SPLITOUT) {
                    __half h00 = __float2half_rn(v00);
                    __half h01 = __float2half_rn(v01);
                    __half h10 = __float2half_rn(v10);
                    __half h11 = __float2half_rn(v11);
                    __half2 hh0 = __halves2half2(h00, h01);
                    __half2 hh1 = __halves2half2(h10, h11);
                    __half2 ll0 = __halves2half2(
                        __float2half_rn(v00 - __half2float(h00)),
                        __float2half_rn(v01 - __half2float(h01)));
                    __half2 ll1 = __halves2half2(
                        __float2half_rn(v10 - __half2float(h10)),
                        __float2half_rn(v11 - __half2float(h11)));
                    *reinterpret_cast<__half2*>(Chi + (size_t)r0 * ldc + col) = hh0;
                    *reinterpret_cast<__half2*>(Clo + (size_t)r0 * ldc + col) = ll0;
                    *reinterpret_cast<__half2*>(Chi + (size_t)(r0 + 8) * ldc + col) = hh1;
                    *reinterpret_cast<__half2*>(Clo + (size_t)(r0 + 8) * ldc + col) = ll1;
                } else {
                    *reinterpret_cast<float2*>(C + (size_t)r0 * ldc + col) =
                        make_float2(v00, v01);
                    *reinterpret_cast<float2*>(C + (size_t)(r0 + 8) * ldc + col) =
                        make_float2(v10, v11);
                }
            }
        }
        if (STATS) {
#pragma unroll
            for (int o = 16; o >= 4; o >>= 1) {
                s0 += __shfl_down_sync(0xffffffffu, s0, o);
                s1 += __shfl_down_sync(0xffffffffu, s1, o);
                q0 += __shfl_down_sync(0xffffffffu, q0, o);
                q1 += __shfl_down_sync(0xffffffffu, q1, o);
            }
            if (lane < 4 && col < Nreal) {
                atomicAdd(&g_bnsum[col], s0);
                atomicAdd(&g_bnsum[col + 1], s1);
                atomicAdd(&g_bnss[col], q0);
                atomicAdd(&g_bnss[col + 1], q1);
            }
        }
    }
}

// ---------------- graph structure ----------------
__global__ void zero_graphbufs_kernel() {
    int i = blockIdx.x * blockDim.x + threadIdx.x;
    int stride = gridDim.x * blockDim.x;
    for (int j = i; j < NNODES * 8; j += stride) g_cnt[j] = 0;
    for (int j = i; j <= NNODES; j += stride) g_cursor[j] = 0;
}

__global__ void edge_count_kernel(const int* __restrict__ ei,
                                  const int* __restrict__ ea) {
    int e = blockIdx.x * blockDim.x + threadIdx.x;
    if (e >= NEDGES) return;
    int dst = ei[NEDGES + e];
    atomicAdd(&g_cursor[dst], 1);
    atomicAdd(&g_cnt[dst * 8 + (ea[2 * e] & 3)], 1);
    atomicAdd(&g_cnt[dst * 8 + 4 + (ea[2 * e + 1] & 3)], 1);
}

__global__ void scan_blocks_kernel() {
    __shared__ int s[1024];
    int tid = threadIdx.x;
    int gid = blockIdx.x * 1024 + tid;
    int v = (gid <= NNODES) ? g_cursor[gid] : 0;
    s[tid] = v;
    __syncthreads();
    for (int off = 1; off < 1024; off <<= 1) {
        int t = (tid >= off) ? s[tid - off] : 0;
        __syncthreads();
        s[tid] += t;
        __syncthreads();
    }
    if (gid <= NNODES) g_rowptr[gid] = s[tid] - v;
    if (tid == 1023) g_bsums[blockIdx.x] = s[1023];
}

__global__ void scan_sums_kernel() {
    if (threadIdx.x == 0) {
        int acc = 0;
        for (int i = 0; i < NBSCAN; i++) {
            int t = g_bsums[i];
            g_bsums[i] = acc;
            acc += t;
        }
    }
}

__global__ void scan_add_kernel() {
    int gid = blockIdx.x * 1024 + threadIdx.x;
    if (gid <= NNODES) {
        int v = g_rowptr[gid] + g_bsums[blockIdx.x];
        g_rowptr[gid] = v;
        g_cursor[gid] = v;
    }
}

__global__ void fill_csr_kernel(const int* __restrict__ ei) {
    int e = blockIdx.x * blockDim.x + threadIdx.x;
    if (e >= NEDGES) return;
    int dst = ei[NEDGES + e];
    int pos = atomicAdd(&g_cursor[dst], 1);
    g_colidx[pos] = ei[e];
}

// ---------------- features ----------------
__global__ void init_h_kernel(const int* __restrict__ x,
                              const float* __restrict__ ae1,
                              const float* __restrict__ ae2) {
    int idx = blockIdx.x * blockDim.x + threadIdx.x;
    if (idx >= NNODES * C4) return;
    int n = idx / C4, c = (idx % C4) * 4;
    float4 v = f4add(ld4(ae1 + x[2 * n] * EMBD + c),
                     ld4(ae2 + x[2 * n + 1] * EMBD + c));
    st4(g_h + (size_t)n * LDH + c, v);
}

// agg -> split fp16 directly (GEMM1 A operand). BN: relu(h*sc+sh) on the fly.
template <int BN>
__global__ void agg_kernel(const float* __restrict__ ee1,
                           const float* __restrict__ ee2) {
    int idx = blockIdx.x * blockDim.x + threadIdx.x;
    if (idx >= NNODES * 80) return;
    int n = idx / 80, c4 = idx % 80;
    int c = c4 * 4;
    size_t o = (size_t)n * LDH + c;
    if (c4 >= C4) {
        *reinterpret_cast<uint2*>(&g_ahi[o]) = make_uint2(0u, 0u);
        *reinterpret_cast<uint2*>(&g_alo[o]) = make_uint2(0u, 0u);
        return;
    }
    float4 sc, sh;
    if (BN) { sc = ld4(g_bnscale + c); sh = ld4(g_bnshift + c); }
    auto xf = [&](float4 v) -> float4 {
        if (BN) {
            v.x = fmaxf(fmaf(v.x, sc.x, sh.x), 0.f);
            v.y = fmaxf(fmaf(v.y, sc.y, sh.y), 0.f);
            v.z = fmaxf(fmaf(v.z, sc.z, sh.z), 0.f);
            v.w = fmaxf(fmaf(v.w, sc.w, sh.w), 0.f);
        }
        return v;
    };
    float4 acc = xf(ld4(g_h + o));  // self message
    int base = n * 8;
    float c00 = (float)g_cnt[base + 0];
    float c01 = (float)g_cnt[base + 1];
    float c02 = (float)g_cnt[base + 2];
    float c10 = (float)g_cnt[base + 4] + 1.0f;
    float c11 = (float)g_cnt[base + 5];
    float c12 = (float)g_cnt[base + 6];
    acc = f4fma(ld4(ee1 + 0 * EMBD + c), c00, acc);
    acc = f4fma(ld4(ee1 + 1 * EMBD + c), c01, acc);
    acc = f4fma(ld4(ee1 + 2 * EMBD + c), c02, acc);
    acc = f4add(acc, ld4(ee1 + 4 * EMBD + c));
    acc = f4fma(ld4(ee2 + 0 * EMBD + c), c10, acc);
    acc = f4fma(ld4(ee2 + 1 * EMBD + c), c11, acc);
    acc = f4fma(ld4(ee2 + 2 * EMBD + c), c12, acc);
    int rs = g_rowptr[n], re = g_rowptr[n + 1];
    for (int i = rs; i < re; i++) {
        int s = g_colidx[i];
        acc = f4add(acc, xf(ld4(g_h + (size_t)s * LDH + c)));
    }
    __half2 h01 = __floats2half2_rn(acc.x, acc.y);
    __half2 h23 = __floats2half2_rn(acc.z, acc.w);
    __half2 l01 = __floats2half2_rn(acc.x - __half2float(h01.x),
                                    acc.y - __half2float(h01.y));
    __half2 l23 = __floats2half2_rn(acc.z - __half2float(h23.x),
                                    acc.w - __half2float(h23.y));
    *reinterpret_cast<uint2*>(&g_ahi[o]) =
        make_uint2(*reinterpret_cast<uint32_t*>(&h01),
                   *reinterpret_cast<uint32_t*>(&h23));
    *reinterpret_cast<uint2*>(&g_alo[o]) =
        make_uint2(*reinterpret_cast<uint32_t*>(&l01),
                   *reinterpret_cast<uint32_t*>(&l23));
}

// ---------------- BatchNorm (stats from GEMM2 epilogue) ----------------
__global__ void zero_bn_kernel() {
    int c = threadIdx.x;
    if (c < EMBD) { g_bnsum[c] = 0.f; g_bnss[c] = 0.f; }
}

__global__ void bn_finalize_kernel(const float* __restrict__ gamma,
                                   const float* __restrict__ beta) {
    int c = threadIdx.x;
    if (c >= EMBD) return;
    float mean = g_bnsum[c] * (1.0f / NNODES);
    float var = g_bnss[c] * (1.0f / NNODES) - mean * mean;
    float rs = rsqrtf(var + 1e-5f);
    float s = rs * gamma[c];
    g_bnscale[c] = s;
    g_bnshift[c] = beta[c] - mean * s;
}

// ---------------- pooling (BN of last layer folded into pool_div) ----------
__global__ void zero_pool_kernel() {
    int i = blockIdx.x * blockDim.x + threadIdx.x;
    if (i < NGRAPHS * LDH) g_pool[i] = 0.f;
    if (i < NGRAPHS) g_gcnt[i] = 0;
}

__global__ void gcount_kernel(const int* __restrict__ bi) {
    int n = blockIdx.x * blockDim.x + threadIdx.x;
    if (n < NNODES) atomicAdd(&g_gcnt[bi[n]], 1);
}

__global__ void pool_kernel(const int* __restrict__ bi) {
    int idx = blockIdx.x * blockDim.x + threadIdx.x;
    if (idx >= NNODES * C4) return;
    int n = idx / C4, c = (idx % C4) * 4;
    int g = bi[n];
    float4 v = ld4(g_h + (size_t)n * LDH + c);
    float* d = g_pool + (size_t)g * LDH + c;
    atomicAdd(d + 0, v.x);
    atomicAdd(d + 1, v.y);
    atomicAdd(d + 2, v.z);
    atomicAdd(d + 3, v.w);
}

__global__ void pool_div_kernel() {
    int i = blockIdx.x * blockDim.x + threadIdx.x;
    if (i >= NGRAPHS * LDH) return;
    int g = i / LDH, c = i % LDH;
    if (c >= EMBD) { g_pool[i] = 0.f; return; }
    float cnt = fmaxf((float)g_gcnt[g], 1.0f);
    g_pool[i] = fmaf(g_pool[i] / cnt, g_bnscale[c], g_bnshift[c]);
}

// ---------------- L2 row normalize ----------------
__global__ void normalize_kernel(float* __restrict__ f) {
    __shared__ float red[4];
    size_t r = blockIdx.x;
    float* row = f + r * LDH;
    float ss = 0.f;
    for (int c = threadIdx.x; c < EMBD; c += 128) {
        float v = row[c];
        ss += v * v;
    }
    for (int o = 16; o; o >>= 1) ss += __shfl_down_sync(0xffffffffu, ss, o);
    if ((threadIdx.x & 31) == 0) red[threadIdx.x >> 5] = ss;
    __syncthreads();
    if (threadIdx.x == 0) red[0] = rsqrtf(red[0] + red[1] + red[2] + red[3]);
    __syncthreads();
    float s = red[0];
    for (int c = threadIdx.x; c < EMBD; c += 128) row[c] *= s;
}

__global__ void labels_kernel(float* __restrict__ out, int extra) {
    int i = blockIdx.x * blockDim.x + threadIdx.x;
    if (i < extra) out[i] = (float)i;
}

// ---------------- host orchestration ----------------
extern "C" void kernel_launch(void* const* d_in, const int* in_sizes, int n_in,
                              void* d_out, int out_size) {
    const float* ae1 = (const float*)d_in[8];
    const float* ae2 = (const float*)d_in[9];
    const float* ee1 = (const float*)d_in[10];
    const float* ee2 = (const float*)d_in[11];
    const float* W1 = (const float*)d_in[12];
    const float* bm1 = (const float*)d_in[13];
    const float* W2 = (const float*)d_in[14];
    const float* bm2 = (const float*)d_in[15];
    const float* gamma = (const float*)d_in[16];
    const float* beta = (const float*)d_in[17];
    const float* Wp1 = (const float*)d_in[18];
    const float* bp1 = (const float*)d_in[19];
    const float* Wp2 = (const float*)d_in[20];
    const float* bp2 = (const float*)d_in[21];

    float *h, *pool, *feat;
    __half *ahi, *alo, *thi, *tlo, *whi;
    cudaGetSymbolAddress((void**)&h, g_h);
    cudaGetSymbolAddress((void**)&pool, g_pool);
    cudaGetSymbolAddress((void**)&feat, g_feat);
    cudaGetSymbolAddress((void**)&ahi, g_ahi);
    cudaGetSymbolAddress((void**)&alo, g_alo);
    cudaGetSymbolAddress((void**)&thi, g_thi);
    cudaGetSymbolAddress((void**)&tlo, g_tlo);
    cudaGetSymbolAddress((void**)&whi, g_whi);

    cudaFuncSetAttribute(mma_gemm<1, 1, 0>,
                         cudaFuncAttributeMaxDynamicSharedMemorySize, GEMM_SMEM);
    cudaFuncSetAttribute(mma_gemm<0, 0, 1>,
                         cudaFuncAttributeMaxDynamicSharedMemorySize, GEMM_SMEM);
    cudaFuncSetAttribute(mma_gemm<0, 0, 0>,
                         cudaFuncAttributeMaxDynamicSharedMemorySize, GEMM_SMEM);

    const int GN = (NNODES * C4 + 255) / 256;
    const int GN80 = (NNODES * 80 + 255) / 256;
    const int GE = (NEDGES + 255) / 256;
    const int GP = (NGRAPHS * LDH + 255) / 256;
    const int MT = MPAD / 128;  // 1563

    for (int enc = 0; enc < 2; enc++) {
        const int* x = (const int*)d_in[enc * 4 + 0];
        const int* ei = (const int*)d_in[enc * 4 + 1];
        const int* ea = (const int*)d_in[enc * 4 + 2];
        const int* bi = (const int*)d_in[enc * 4 + 3];

        zero_graphbufs_kernel<<<2048, 256>>>();
        edge_count_kernel<<<GE, 256>>>(ei, ea);
        scan_blocks_kernel<<<NBSCAN, 1024>>>();
        scan_sums_kernel<<<1, 32>>>();
        scan_add_kernel<<<NBSCAN, 1024>>>();
        fill_csr_kernel<<<GE, 256>>>(ei);

        init_h_kernel<<<GN, 256>>>(x, ae1, ae2);

        for (int l = 0; l < NLAYERS; l++) {
            if (l == 0)
                agg_kernel<0><<<GN80, 256>>>(ee1 + l * 6 * EMBD, ee2 + l * 3 * EMBD);
            else
                agg_kernel<1><<<GN80, 256>>>(ee1 + l * 6 * EMBD, ee2 + l * 3 * EMBD);

            // GEMM1: agg(split) @ W1(fp16) -> t split fp16 [MPAD x 640], relu
            convert_w_kernel<<<(320 * 640 + 255) / 256, 256>>>(
                W1 + (size_t)l * EMBD * HID, EMBD, HID, 320, 640, whi);
            mma_gemm<1, 1, 0><<<dim3(3, MT), 256, GEMM_SMEM>>>(
                ahi, alo, 320, 320, whi, 640, bm1 + l * HID, 1.0f,
                nullptr, thi, tlo, LDT, HID);

            // GEMM2: t(split) @ W2(fp16) -> h fp32 [MPAD x 320], + column stats
            convert_w_kernel<<<(640 * 320 + 255) / 256, 256>>>(
                W2 + (size_t)l * HID * EMBD, HID, EMBD, 640, 320, whi);
            zero_bn_kernel<<<1, 512>>>();
            mma_gemm<0, 0, 1><<<dim3(2, MT), 256, GEMM_SMEM>>>(
                thi, tlo, LDT, 640, whi, 320, bm2 + l * EMBD, 1.0f,
                h, nullptr, nullptr, LDH, EMBD);
            bn_finalize_kernel<<<1, 512>>>(gamma + l * EMBD, beta + l * EMBD);
        }

        // mean pool of BN(h_last): accumulate raw h, fold BN into the divide
        zero_pool_kernel<<<GP, 256>>>();
        gcount_kernel<<<(NNODES + 255) / 256, 256>>>(bi);
        pool_kernel<<<GN, 256>>>(bi);
        pool_div_kernel<<<GP, 256>>>();

        // projection head (M=4096)
        convert_split_kernel<<<GP, 256>>>(pool, NGRAPHS * LDH, ahi, alo);
        convert_w_kernel<<<(320 * 320 + 255) / 256, 256>>>(
            Wp1, EMBD, EMBD, 320, 320, whi);
        mma_gemm<1, 1, 0><<<dim3(2, NGRAPHS / 128), 256, GEMM_SMEM>>>(
            ahi, alo, 320, 320, whi, 320, bp1, 1.0f,
            nullptr, thi, tlo, 320, EMBD);
        convert_w_kernel<<<(320 * 320 + 255) / 256, 256>>>(
            Wp2, EMBD, EMBD, 320, 320, whi);
        mma_gemm<0, 0, 0><<<dim3(2, NGRAPHS / 128), 256, GEMM_SMEM>>>(
            thi, tlo, 320, 320, whi, 320, bp2, 1.0f,
            feat + (size_t)enc * NGRAPHS * LDH, nullptr, nullptr, LDH, EMBD);
    }

    normalize_kernel<<<2 * NGRAPHS, 128>>>(feat);

    // logits = 25 * f0 @ f1^T : f0 split (A), f1 single fp16 (B)
    convert_split_kernel<<<GP, 256>>>(feat, NGRAPHS * LDH, ahi, alo);
    convert_h_kernel<<<GP, 256>>>(feat + (size_t)NGRAPHS * LDH,
                                  NGRAPHS * LDH, thi);
    mma_gemm<0, 0, 0><<<dim3(NGRAPHS / 256, NGRAPHS / 128), 256, GEMM_SMEM>>>(
        ahi, alo, 320, 320, thi, NGRAPHS,
        nullptr, 25.0f, (float*)d_out, nullptr, nullptr, NGRAPHS, NGRAPHS);

    long long logits_elems = (long long)NGRAPHS * NGRAPHS;
    int extra = (int)((long long)out_size - logits_elems);
    if (extra > 0)
        labels_kernel<<<(extra + 255) / 256, 256>>>(
            (float*)d_out + logits_elems, extra);
}